// round 10
// baseline (speedup 1.0000x reference)
#include <cuda_runtime.h>
#include <cuda_bf16.h>
#include <cstdint>

// ===========================================================================
// GCN_81776177316393 — bf16x3-split GEMMs on mma.sync (HMMA; tcgen05 not
// compilable: harness ptxas targets plain sm_103). R10: cp.async 4-stage
// pipeline + graph-parallel GCN branch + conv placed at capture index 3.
//   feats = relu(conv1d(x, conv_w, pad=1)) : [4,3,512,2048]
//   a     = row_norm(max(adj,adj^T)+I)     : [4,256,256]
//   h     = relu(a @ (nodes@W1) + b1)
//   out   = a @ (h@W2) + b2                : [4,256,2048]
// ===========================================================================

typedef unsigned long long ull;

// -------------------- scratch (static device globals) ----------------------
__device__ __align__(16) __nv_bfloat16 g_xh[12u * 512u * 2048u];
__device__ __align__(16) __nv_bfloat16 g_xl[12u * 512u * 2048u];
__device__ __align__(16) __nv_bfloat16 g_wth[2048u * 6144u];   // B^T: [co][tap*2048+ci]
__device__ __align__(16) __nv_bfloat16 g_wtl[2048u * 6144u];
__device__ __align__(16) __nv_bfloat16 g_w1h[2048u * 2048u];   // W1^T: [n][k]
__device__ __align__(16) __nv_bfloat16 g_w1l[2048u * 2048u];
__device__ __align__(16) __nv_bfloat16 g_w2h[2048u * 2048u];
__device__ __align__(16) __nv_bfloat16 g_w2l[2048u * 2048u];
__device__ __align__(16) __nv_bfloat16 g_nh[1024u * 2048u];
__device__ __align__(16) __nv_bfloat16 g_nl[1024u * 2048u];
__device__ __align__(16) __nv_bfloat16 g_hh[1024u * 2048u];
__device__ __align__(16) __nv_bfloat16 g_hl[1024u * 2048u];
__device__ float g_anorm[4 * 256 * 256];
__device__ float g_h1[1024u * 2048u];
__device__ float g_h2[1024u * 2048u];

// -------------------- pre-created stream/events (module load, pre-capture) --
static cudaStream_t g_s2 = nullptr;
static cudaEvent_t g_ev_fork = nullptr, g_ev_join = nullptr;
namespace {
struct StreamInit {
    StreamInit() {
        if (cudaStreamCreateWithFlags(&g_s2, cudaStreamNonBlocking) != cudaSuccess)
            g_s2 = nullptr;
        if (cudaEventCreateWithFlags(&g_ev_fork, cudaEventDisableTiming) != cudaSuccess)
            g_ev_fork = nullptr;
        if (cudaEventCreateWithFlags(&g_ev_join, cudaEventDisableTiming) != cudaSuccess)
            g_ev_join = nullptr;
    }
};
StreamInit g_stream_init;
}

// -------------------- PTX helpers ------------------------------------------
__device__ __forceinline__ uint32_t smem_u32(const void* p) {
    uint32_t a;
    asm("{ .reg .u64 t; cvta.to.shared.u64 t, %1; cvt.u32.u64 %0, t; }"
        : "=r"(a) : "l"(p));
    return a;
}
__device__ __forceinline__ void ldsm4(uint32_t& r0, uint32_t& r1,
                                      uint32_t& r2, uint32_t& r3, uint32_t addr) {
    asm volatile("ldmatrix.sync.aligned.m8n8.x4.shared.b16 {%0,%1,%2,%3}, [%4];"
                 : "=r"(r0), "=r"(r1), "=r"(r2), "=r"(r3) : "r"(addr));
}
__device__ __forceinline__ void mma16816(float* d, const uint32_t* a, const uint32_t* b) {
    asm volatile("mma.sync.aligned.m16n8k16.row.col.f32.bf16.bf16.f32 "
                 "{%0,%1,%2,%3}, {%4,%5,%6,%7}, {%8,%9}, {%0,%1,%2,%3};"
                 : "+f"(d[0]), "+f"(d[1]), "+f"(d[2]), "+f"(d[3])
                 : "r"(a[0]), "r"(a[1]), "r"(a[2]), "r"(a[3]), "r"(b[0]), "r"(b[1]));
}
// 16B async copy, L2-cached; src_size=0 -> zero-fill (conv halo padding)
__device__ __forceinline__ void cp16(uint32_t dst, const void* src, uint32_t sz) {
    asm volatile("cp.async.cg.shared.global [%0], [%1], 16, %2;"
                 :: "r"(dst), "l"(src), "r"(sz) : "memory");
}
#define CP_COMMIT() asm volatile("cp.async.commit_group;" ::: "memory")
#define CP_WAIT2()  asm volatile("cp.async.wait_group 2;" ::: "memory")

// -------------------- preprocessing kernels --------------------------------
__global__ void split_kernel(const float* __restrict__ s, __nv_bfloat16* __restrict__ h,
                             __nv_bfloat16* __restrict__ l, int n) {
    int i = blockIdx.x * blockDim.x + threadIdx.x;
    int stride = gridDim.x * blockDim.x;
    for (; i < n; i += stride) {
        float v = s[i];
        __nv_bfloat16 hv = __float2bfloat16(v);
        h[i] = hv;
        l[i] = __float2bfloat16(v - __bfloat162float(hv));
    }
}

// conv_w[co][ci][tap] -> g_wth/g_wtl [co][tap*2048+ci]
__global__ void convw_split_kernel(const float* __restrict__ w) {
    __shared__ float row[6144];
    int co = blockIdx.x;
    const float* src = w + (size_t)co * 6144;
    for (int j = threadIdx.x; j < 6144; j += 256) row[j] = src[j];
    __syncthreads();
    size_t base = (size_t)co * 6144;
    for (int kk = threadIdx.x; kk < 6144; kk += 256) {
        int tap = kk >> 11, ci = kk & 2047;
        float v = row[ci * 3 + tap];
        __nv_bfloat16 hv = __float2bfloat16(v);
        g_wth[base + kk] = hv;
        g_wtl[base + kk] = __float2bfloat16(v - __bfloat162float(hv));
    }
}

// W[k][n] -> out_hi/lo [n][k]
__global__ void transw_split_kernel(const float* __restrict__ W,
                                    __nv_bfloat16* __restrict__ oh,
                                    __nv_bfloat16* __restrict__ ol) {
    __shared__ float tile[32][33];
    int n0 = blockIdx.x * 32, k0 = blockIdx.y * 32;
    int tx = threadIdx.x, ty = threadIdx.y;
#pragma unroll
    for (int yy = 0; yy < 4; yy++)
        tile[ty + yy * 8][tx] = W[(size_t)(k0 + ty + yy * 8) * 2048 + n0 + tx];
    __syncthreads();
#pragma unroll
    for (int yy = 0; yy < 4; yy++) {
        float v = tile[tx][ty + yy * 8];
        size_t o = (size_t)(n0 + ty + yy * 8) * 2048 + k0 + tx;
        __nv_bfloat16 hv = __float2bfloat16(v);
        oh[o] = hv;
        ol[o] = __float2bfloat16(v - __bfloat162float(hv));
    }
}

// a = max(adj, adj^T) + I, row-normalized
__global__ void norm_adj_kernel(const float* __restrict__ adj) {
    int b = blockIdx.x >> 8;
    int i = blockIdx.x & 255;
    int t = threadIdx.x;
    const float* ab = adj + (size_t)b * 65536;
    float v = fmaxf(ab[i * 256 + t], ab[t * 256 + i]) + (t == i ? 1.0f : 0.0f);
    __shared__ float red[256];
    red[t] = v;
    __syncthreads();
#pragma unroll
    for (int s = 128; s > 0; s >>= 1) {
        if (t < s) red[t] += red[t + s];
        __syncthreads();
    }
    float rs = red[0];
    float inv = rs > 0.0f ? 1.0f / rs : 0.0f;
    g_anorm[(size_t)b * 65536 + i * 256 + t] = v * inv;
}

// -------------------- HMMA bf16x3 GEMM, cp.async 4-stage --------------------
// C[M,N] = A[M,K] @ B^T[N,K] (+bias, optional relu), fp32 via hi/lo bf16.
// Tile: BM=128, BN=128, BK=32. 256 threads, 8 warps = 2(M) x 4(N), warp 64x32.
// Smem rows skewed to 80B stride -> conflict-free ldmatrix/cp.async.
// CONV=true: A is im2col of x[12][512][2048]; chunk kt -> tap = kt>>11.
#define MM_STAGE 40960                       // 4 regions * 128 rows * 80B
#define MM_NSTG  4
#define MM_SMEM  (MM_NSTG * MM_STAGE)        // 160 KB
#define OA_L 10240
#define OB_H 20480
#define OB_L 30720

template <bool CONV>
__global__ void __launch_bounds__(256, 1)
mma_gemm(const __nv_bfloat16* __restrict__ Ah, const __nv_bfloat16* __restrict__ Al,
         const __nv_bfloat16* __restrict__ Bh, const __nv_bfloat16* __restrict__ Bl,
         float* __restrict__ C, const float* __restrict__ bias, int relu,
         int K, int N)
{
    extern __shared__ __align__(128) char smem[];
    const uint32_t sbase = smem_u32(smem);
    const int tid  = threadIdx.x;
    const int lane = tid & 31;
    const int wid  = tid >> 5;
    const int bm = blockIdx.y * 128;
    const int bn = blockIdx.x * 128;
    const int wm = (wid & 1) * 64;
    const int wn = (wid >> 1) * 32;
    const int nch = K >> 5;

    uint32_t aoff[4];
#pragma unroll
    for (int mt = 0; mt < 4; mt++)
        aoff[mt] = (uint32_t)(wm + mt * 16 + (lane & 15)) * 80 + ((lane >> 4) * 16);
    const uint32_t boff = (uint32_t)(wn + lane) * 80;

    float acc[4][4][4];
#pragma unroll
    for (int i = 0; i < 4; i++)
#pragma unroll
        for (int j = 0; j < 4; j++)
#pragma unroll
            for (int r = 0; r < 4; r++) acc[i][j][r] = 0.0f;

    // per-thread loader geometry (8 x 16B cp.async per stage)
    const int l_r0 = tid >> 2;                // rows r0, r0+64
    const int l_cq = tid & 3;                 // 16B segment 0..3
    const uint32_t l_soff = (uint32_t)l_r0 * 80 + l_cq * 16;

    auto issue_stage = [&](int c, int slot) {
        const int kt = c << 5;
        const uint32_t sbs = sbase + slot * MM_STAGE;
        int tap = 0, ci0 = 0;
        if (CONV) { tap = kt >> 11; ci0 = kt & 2047; }
#pragma unroll
        for (int it = 0; it < 2; it++) {
            int row = l_r0 + it * 64;
            int cb = l_cq * 8;
            uint32_t off = l_soff + (uint32_t)it * (64 * 80);
            uint32_t asz = 16;
            size_t go;
            if (CONV) {
                int m = bm + row;
                int b = m >> 9;
                int t = (m & 511) - 1 + tap;
                bool ok = ((unsigned)t < 512u);
                go = ((size_t)b * 512 + (ok ? t : 0)) * 2048 + ci0 + cb;
                asz = ok ? 16u : 0u;
            } else {
                go = (size_t)(bm + row) * K + kt + cb;
            }
            size_t gb = (size_t)(bn + row) * K + kt + cb;
            cp16(sbs + off,        Ah + go, asz);
            cp16(sbs + OA_L + off, Al + go, asz);
            cp16(sbs + OB_H + off, Bh + gb, 16u);
            cp16(sbs + OB_L + off, Bl + gb, 16u);
        }
    };

    auto compute = [&](int buf) {
        uint32_t sb = sbase + buf * MM_STAGE;
#pragma unroll
        for (int h = 0; h < 2; h++) {
            uint32_t hb = (uint32_t)h * 32;
            uint32_t fah[4][4], fal[4][4], fbh[4][2], fbl[4][2];
#pragma unroll
            for (int mt = 0; mt < 4; mt++) {
                ldsm4(fah[mt][0], fah[mt][1], fah[mt][2], fah[mt][3],
                      sb + aoff[mt] + hb);
                ldsm4(fal[mt][0], fal[mt][1], fal[mt][2], fal[mt][3],
                      sb + OA_L + aoff[mt] + hb);
            }
            ldsm4(fbh[0][0], fbh[1][0], fbh[2][0], fbh[3][0], sb + OB_H + boff + hb);
            ldsm4(fbh[0][1], fbh[1][1], fbh[2][1], fbh[3][1], sb + OB_H + boff + hb + 16);
            ldsm4(fbl[0][0], fbl[1][0], fbl[2][0], fbl[3][0], sb + OB_L + boff + hb);
            ldsm4(fbl[0][1], fbl[1][1], fbl[2][1], fbl[3][1], sb + OB_L + boff + hb + 16);
#pragma unroll
            for (int mt = 0; mt < 4; mt++)
#pragma unroll
                for (int nt = 0; nt < 4; nt++) {
                    mma16816(acc[mt][nt], fah[mt], fbh[nt]);   // hi*hi
                    mma16816(acc[mt][nt], fah[mt], fbl[nt]);   // hi*lo
                    mma16816(acc[mt][nt], fal[mt], fbh[nt]);   // lo*hi
                }
        }
    };

    // prologue: prefetch 3 stages
#pragma unroll
    for (int p = 0; p < 3; p++) {
        if (p < nch) issue_stage(p, p);
        CP_COMMIT();
    }
    // mainloop
    for (int c = 0; c < nch; c++) {
        CP_WAIT2();                // stage c landed
        __syncthreads();           // all warps: stage c visible, stage c-1 consumed
        compute(c & 3);
        int p = c + 3;
        if (p < nch) issue_stage(p, p & 3);
        CP_COMMIT();
    }

    // epilogue: c0,c1 -> (row, col..col+1); c2,c3 -> (row+8, ...)
    const int r0 = lane >> 2, cp = (lane & 3) * 2;
#pragma unroll
    for (int mt = 0; mt < 4; mt++) {
        int row = bm + wm + mt * 16 + r0;
#pragma unroll
        for (int nt = 0; nt < 4; nt++) {
            int col = bn + wn + nt * 8 + cp;
            float b0 = bias ? __ldg(bias + col) : 0.0f;
            float b1 = bias ? __ldg(bias + col + 1) : 0.0f;
            float o0 = acc[mt][nt][0] + b0, o1 = acc[mt][nt][1] + b1;
            float o2 = acc[mt][nt][2] + b0, o3 = acc[mt][nt][3] + b1;
            if (relu) {
                o0 = fmaxf(o0, 0.f); o1 = fmaxf(o1, 0.f);
                o2 = fmaxf(o2, 0.f); o3 = fmaxf(o3, 0.f);
            }
            *(float2*)(C + (size_t)row * N + col)       = make_float2(o0, o1);
            *(float2*)(C + (size_t)(row + 8) * N + col) = make_float2(o2, o3);
        }
    }
}

// -------------------- FFMA2 GEMM (small batched a@H) ------------------------
#define BM 128
#define BN 128
#define BK 16
#define APAD 4

__device__ __forceinline__ ull pack2(float lo, float hi) {
    ull r; asm("mov.b64 %0, {%1, %2};" : "=l"(r) : "f"(lo), "f"(hi)); return r;
}
__device__ __forceinline__ void fma2(ull& d, ull a, ull b) {
    asm("fma.rn.f32x2 %0, %1, %2, %0;" : "+l"(d) : "l"(a), "l"(b));
}
__device__ __forceinline__ float2 unpack2(ull v) {
    float2 f; asm("mov.b64 {%0, %1}, %2;" : "=f"(f.x), "=f"(f.y) : "l"(v)); return f;
}

__global__ void __launch_bounds__(256, 2)
ffma_gemm(const float* __restrict__ A, size_t sA,
          const float* __restrict__ B, size_t sB,
          float* __restrict__ C, size_t sC,
          const float* __restrict__ bias, int do_relu,
          int M, int N, int K)
{
    A += (size_t)blockIdx.z * sA;
    B += (size_t)blockIdx.z * sB;
    C += (size_t)blockIdx.z * sC;
    const int bm = blockIdx.y * BM;
    const int bn = blockIdx.x * BN;

    __shared__ float As[2][BK][BM + APAD];
    __shared__ float Bs[2][BK][BN];

    const int tid = threadIdx.x;
    const int tx = tid & 15;
    const int ty = tid >> 4;
    const int a_r = tid >> 2;
    const int a_c = (tid & 3) * 4;
    const int b_r = tid >> 5;
    const int b_c = (tid & 31) * 4;

    ull acc[8][4];
#pragma unroll
    for (int i = 0; i < 8; i++)
#pragma unroll
        for (int j = 0; j < 4; j++) acc[i][j] = 0ull;

    float4 ra0, ra1, rb0, rb1;

    auto load_tiles = [&](int kt) {
        ra0 = *(const float4*)(A + (size_t)(bm + a_r) * K + kt + a_c);
        ra1 = *(const float4*)(A + (size_t)(bm + a_r + 64) * K + kt + a_c);
        rb0 = *(const float4*)(B + (size_t)(kt + b_r) * N + bn + b_c);
        rb1 = *(const float4*)(B + (size_t)(kt + b_r + 8) * N + bn + b_c);
    };
    auto store_tiles = [&](int buf) {
        As[buf][a_c + 0][a_r] = ra0.x; As[buf][a_c + 1][a_r] = ra0.y;
        As[buf][a_c + 2][a_r] = ra0.z; As[buf][a_c + 3][a_r] = ra0.w;
        As[buf][a_c + 0][a_r + 64] = ra1.x; As[buf][a_c + 1][a_r + 64] = ra1.y;
        As[buf][a_c + 2][a_r + 64] = ra1.z; As[buf][a_c + 3][a_r + 64] = ra1.w;
        *(float4*)&Bs[buf][b_r][b_c] = rb0;
        *(float4*)&Bs[buf][b_r + 8][b_c] = rb1;
    };
    auto compute = [&](int buf) {
#pragma unroll
        for (int k = 0; k < BK; k++) {
            float4 a0 = *(const float4*)&As[buf][k][ty * 8];
            float4 a1 = *(const float4*)&As[buf][k][ty * 8 + 4];
            float4 b0 = *(const float4*)&Bs[buf][k][tx * 8];
            float4 b1 = *(const float4*)&Bs[buf][k][tx * 8 + 4];
            ull bp0 = pack2(b0.x, b0.y), bp1 = pack2(b0.z, b0.w);
            ull bp2 = pack2(b1.x, b1.y), bp3 = pack2(b1.z, b1.w);
            float av[8] = {a0.x, a0.y, a0.z, a0.w, a1.x, a1.y, a1.z, a1.w};
#pragma unroll
            for (int i = 0; i < 8; i++) {
                ull ap = pack2(av[i], av[i]);
                fma2(acc[i][0], ap, bp0); fma2(acc[i][1], ap, bp1);
                fma2(acc[i][2], ap, bp2); fma2(acc[i][3], ap, bp3);
            }
        }
    };

    load_tiles(0);
    store_tiles(0);
    __syncthreads();
    int buf = 0;
    for (int kt = BK;; kt += BK) {
        bool more = kt < K;
        if (more) load_tiles(kt);
        compute(buf);
        if (!more) break;
        store_tiles(buf ^ 1);
        __syncthreads();
        buf ^= 1;
    }

    float bv[8];
#pragma unroll
    for (int j = 0; j < 8; j++) bv[j] = bias ? bias[bn + tx * 8 + j] : 0.0f;

#pragma unroll
    for (int i = 0; i < 8; i++) {
        float o[8];
        float2 p;
        p = unpack2(acc[i][0]); o[0] = p.x + bv[0]; o[1] = p.y + bv[1];
        p = unpack2(acc[i][1]); o[2] = p.x + bv[2]; o[3] = p.y + bv[3];
        p = unpack2(acc[i][2]); o[4] = p.x + bv[4]; o[5] = p.y + bv[5];
        p = unpack2(acc[i][3]); o[6] = p.x + bv[6]; o[7] = p.y + bv[7];
        if (do_relu) {
#pragma unroll
            for (int j = 0; j < 8; j++) o[j] = fmaxf(o[j], 0.0f);
        }
        size_t off = (size_t)(bm + ty * 8 + i) * N + bn + tx * 8;
        *(float4*)(C + off)     = make_float4(o[0], o[1], o[2], o[3]);
        *(float4*)(C + off + 4) = make_float4(o[4], o[5], o[6], o[7]);
    }
}

// ---------------------------------------------------------------------------
extern "C" void kernel_launch(void* const* d_in, const int* in_sizes, int n_in,
                              void* d_out, int out_size) {
    const float* x      = (const float*)d_in[0];
    const float* nodes  = (const float*)d_in[1];
    const float* adj    = (const float*)d_in[2];
    const float* conv_w = (const float*)d_in[3];
    const float* conv_b = (const float*)d_in[4];
    const float* W1     = (const float*)d_in[5];
    const float* b1     = (const float*)d_in[6];
    const float* W2     = (const float*)d_in[7];
    const float* b2     = (const float*)d_in[8];

    float* feats   = (float*)d_out;
    float* gcn_out = (float*)d_out + (size_t)12 * 512 * 2048;

    __nv_bfloat16 *xh, *xl, *wth, *wtl, *w1h, *w1l, *w2h, *w2l, *nh, *nl, *hh, *hl;
    float *anorm, *h1, *h2;
    cudaGetSymbolAddress((void**)&xh, g_xh);   cudaGetSymbolAddress((void**)&xl, g_xl);
    cudaGetSymbolAddress((void**)&wth, g_wth); cudaGetSymbolAddress((void**)&wtl, g_wtl);
    cudaGetSymbolAddress((void**)&w1h, g_w1h); cudaGetSymbolAddress((void**)&w1l, g_w1l);
    cudaGetSymbolAddress((void**)&w2h, g_w2h); cudaGetSymbolAddress((void**)&w2l, g_w2l);
    cudaGetSymbolAddress((void**)&nh, g_nh);   cudaGetSymbolAddress((void**)&nl, g_nl);
    cudaGetSymbolAddress((void**)&hh, g_hh);   cudaGetSymbolAddress((void**)&hl, g_hl);
    cudaGetSymbolAddress((void**)&anorm, g_anorm);
    cudaGetSymbolAddress((void**)&h1, g_h1);   cudaGetSymbolAddress((void**)&h2, g_h2);

    cudaFuncSetAttribute((const void*)mma_gemm<true>,
                         cudaFuncAttributeMaxDynamicSharedMemorySize, MM_SMEM);
    cudaFuncSetAttribute((const void*)mma_gemm<false>,
                         cudaFuncAttributeMaxDynamicSharedMemorySize, MM_SMEM);

    const bool fork = (g_s2 != nullptr) && (g_ev_fork != nullptr) && (g_ev_join != nullptr);
    cudaStream_t sB = fork ? g_s2 : (cudaStream_t)0;

    // fork branch B (GCN chain) off the capture stream before any work
    if (fork) {
        cudaEventRecord(g_ev_fork, 0);
        cudaStreamWaitEvent(g_s2, g_ev_fork, 0);
    }

    // --- branch A (conv path, capture stream); conv = 4th kernel issued ---
    convw_split_kernel<<<2048, 256>>>(conv_w);                       // (0)
    split_kernel<<<4096, 256>>>(x, xh, xl, 12 * 512 * 2048);         // (1)
    norm_adj_kernel<<<1024, 256, 0, sB>>>(adj);                      // (2, branch B)
    mma_gemm<true><<<dim3(16, 48), 256, MM_SMEM>>>(                  // (3) <- profiled
        xh, xl, wth, wtl, feats, conv_b, 1, 6144, 2048);

    // --- branch B (GCN chain), independent of conv ---
    transw_split_kernel<<<dim3(64, 64), dim3(32, 8), 0, sB>>>(W1, w1h, w1l);
    transw_split_kernel<<<dim3(64, 64), dim3(32, 8), 0, sB>>>(W2, w2h, w2l);
    split_kernel<<<2048, 256, 0, sB>>>(nodes, nh, nl, 1024 * 2048);
    mma_gemm<false><<<dim3(16, 8), 256, MM_SMEM, sB>>>(
        nh, nl, w1h, w1l, h1, nullptr, 0, 2048, 2048);
    ffma_gemm<<<dim3(16, 2, 4), 256, 0, sB>>>(
        anorm, 65536, h1, 524288, h2, 524288, b1, 1, 256, 2048, 256);
    split_kernel<<<2048, 256, 0, sB>>>(h2, hh, hl, 1024 * 2048);
    mma_gemm<false><<<dim3(16, 8), 256, MM_SMEM, sB>>>(
        hh, hl, w2h, w2l, h1, nullptr, 0, 2048, 2048);
    ffma_gemm<<<dim3(16, 2, 4), 256, 0, sB>>>(
        anorm, 65536, h1, 524288, gcn_out, 524288, b2, 0, 256, 2048, 256);

    // join branch B back into the capture stream
    if (fork) {
        cudaEventRecord(g_ev_join, g_s2);
        cudaStreamWaitEvent((cudaStream_t)0, g_ev_join, 0);
    }

    (void)in_sizes; (void)n_in; (void)out_size;
}

// round 11
// speedup vs baseline: 1.6397x; 1.6397x over previous
#include <cuda_runtime.h>
#include <cuda_bf16.h>
#include <cstdint>

// ===========================================================================
// GCN_81776177316393 — bf16x3-split GEMMs on mma.sync (HMMA; tcgen05 not
// compilable: harness ptxas targets plain sm_103). R11: cp.async 2-stage
// (80KB smem -> 2 CTAs/SM restored; R10's 160KB/4-stage dropped occupancy to
// 1 CTA/SM and regressed) + graph-parallel GCN branch kept.
//   feats = relu(conv1d(x, conv_w, pad=1)) : [4,3,512,2048]
//   a     = row_norm(max(adj,adj^T)+I)     : [4,256,256]
//   h     = relu(a @ (nodes@W1) + b1)
//   out   = a @ (h@W2) + b2                : [4,256,2048]
// ===========================================================================

typedef unsigned long long ull;

// -------------------- scratch (static device globals) ----------------------
__device__ __align__(16) __nv_bfloat16 g_xh[12u * 512u * 2048u];
__device__ __align__(16) __nv_bfloat16 g_xl[12u * 512u * 2048u];
__device__ __align__(16) __nv_bfloat16 g_wth[2048u * 6144u];   // B^T: [co][tap*2048+ci]
__device__ __align__(16) __nv_bfloat16 g_wtl[2048u * 6144u];
__device__ __align__(16) __nv_bfloat16 g_w1h[2048u * 2048u];   // W1^T: [n][k]
__device__ __align__(16) __nv_bfloat16 g_w1l[2048u * 2048u];
__device__ __align__(16) __nv_bfloat16 g_w2h[2048u * 2048u];
__device__ __align__(16) __nv_bfloat16 g_w2l[2048u * 2048u];
__device__ __align__(16) __nv_bfloat16 g_nh[1024u * 2048u];
__device__ __align__(16) __nv_bfloat16 g_nl[1024u * 2048u];
__device__ __align__(16) __nv_bfloat16 g_hh[1024u * 2048u];
__device__ __align__(16) __nv_bfloat16 g_hl[1024u * 2048u];
__device__ float g_anorm[4 * 256 * 256];
__device__ float g_h1[1024u * 2048u];
__device__ float g_h2[1024u * 2048u];

// -------------------- pre-created stream/events (module load, pre-capture) --
static cudaStream_t g_s2 = nullptr;
static cudaEvent_t g_ev_fork = nullptr, g_ev_join = nullptr;
namespace {
struct StreamInit {
    StreamInit() {
        if (cudaStreamCreateWithFlags(&g_s2, cudaStreamNonBlocking) != cudaSuccess)
            g_s2 = nullptr;
        if (cudaEventCreateWithFlags(&g_ev_fork, cudaEventDisableTiming) != cudaSuccess)
            g_ev_fork = nullptr;
        if (cudaEventCreateWithFlags(&g_ev_join, cudaEventDisableTiming) != cudaSuccess)
            g_ev_join = nullptr;
    }
};
StreamInit g_stream_init;
}

// -------------------- PTX helpers ------------------------------------------
__device__ __forceinline__ uint32_t smem_u32(const void* p) {
    uint32_t a;
    asm("{ .reg .u64 t; cvta.to.shared.u64 t, %1; cvt.u32.u64 %0, t; }"
        : "=r"(a) : "l"(p));
    return a;
}
__device__ __forceinline__ void ldsm4(uint32_t& r0, uint32_t& r1,
                                      uint32_t& r2, uint32_t& r3, uint32_t addr) {
    asm volatile("ldmatrix.sync.aligned.m8n8.x4.shared.b16 {%0,%1,%2,%3}, [%4];"
                 : "=r"(r0), "=r"(r1), "=r"(r2), "=r"(r3) : "r"(addr));
}
__device__ __forceinline__ void mma16816(float* d, const uint32_t* a, const uint32_t* b) {
    asm volatile("mma.sync.aligned.m16n8k16.row.col.f32.bf16.bf16.f32 "
                 "{%0,%1,%2,%3}, {%4,%5,%6,%7}, {%8,%9}, {%0,%1,%2,%3};"
                 : "+f"(d[0]), "+f"(d[1]), "+f"(d[2]), "+f"(d[3])
                 : "r"(a[0]), "r"(a[1]), "r"(a[2]), "r"(a[3]), "r"(b[0]), "r"(b[1]));
}
// 16B async copy, L2-cached; src_size=0 -> zero-fill (conv halo padding)
__device__ __forceinline__ void cp16(uint32_t dst, const void* src, uint32_t sz) {
    asm volatile("cp.async.cg.shared.global [%0], [%1], 16, %2;"
                 :: "r"(dst), "l"(src), "r"(sz) : "memory");
}
#define CP_COMMIT() asm volatile("cp.async.commit_group;" ::: "memory")
#define CP_WAIT0()  asm volatile("cp.async.wait_group 0;" ::: "memory")

// -------------------- preprocessing kernels --------------------------------
__global__ void split_kernel(const float* __restrict__ s, __nv_bfloat16* __restrict__ h,
                             __nv_bfloat16* __restrict__ l, int n) {
    int i = blockIdx.x * blockDim.x + threadIdx.x;
    int stride = gridDim.x * blockDim.x;
    for (; i < n; i += stride) {
        float v = s[i];
        __nv_bfloat16 hv = __float2bfloat16(v);
        h[i] = hv;
        l[i] = __float2bfloat16(v - __bfloat162float(hv));
    }
}

// conv_w[co][ci][tap] -> g_wth/g_wtl [co][tap*2048+ci]
__global__ void convw_split_kernel(const float* __restrict__ w) {
    __shared__ float row[6144];
    int co = blockIdx.x;
    const float* src = w + (size_t)co * 6144;
    for (int j = threadIdx.x; j < 6144; j += 256) row[j] = src[j];
    __syncthreads();
    size_t base = (size_t)co * 6144;
    for (int kk = threadIdx.x; kk < 6144; kk += 256) {
        int tap = kk >> 11, ci = kk & 2047;
        float v = row[ci * 3 + tap];
        __nv_bfloat16 hv = __float2bfloat16(v);
        g_wth[base + kk] = hv;
        g_wtl[base + kk] = __float2bfloat16(v - __bfloat162float(hv));
    }
}

// W[k][n] -> out_hi/lo [n][k]
__global__ void transw_split_kernel(const float* __restrict__ W,
                                    __nv_bfloat16* __restrict__ oh,
                                    __nv_bfloat16* __restrict__ ol) {
    __shared__ float tile[32][33];
    int n0 = blockIdx.x * 32, k0 = blockIdx.y * 32;
    int tx = threadIdx.x, ty = threadIdx.y;
#pragma unroll
    for (int yy = 0; yy < 4; yy++)
        tile[ty + yy * 8][tx] = W[(size_t)(k0 + ty + yy * 8) * 2048 + n0 + tx];
    __syncthreads();
#pragma unroll
    for (int yy = 0; yy < 4; yy++) {
        float v = tile[tx][ty + yy * 8];
        size_t o = (size_t)(n0 + ty + yy * 8) * 2048 + k0 + tx;
        __nv_bfloat16 hv = __float2bfloat16(v);
        oh[o] = hv;
        ol[o] = __float2bfloat16(v - __bfloat162float(hv));
    }
}

// a = max(adj, adj^T) + I, row-normalized
__global__ void norm_adj_kernel(const float* __restrict__ adj) {
    int b = blockIdx.x >> 8;
    int i = blockIdx.x & 255;
    int t = threadIdx.x;
    const float* ab = adj + (size_t)b * 65536;
    float v = fmaxf(ab[i * 256 + t], ab[t * 256 + i]) + (t == i ? 1.0f : 0.0f);
    __shared__ float red[256];
    red[t] = v;
    __syncthreads();
#pragma unroll
    for (int s = 128; s > 0; s >>= 1) {
        if (t < s) red[t] += red[t + s];
        __syncthreads();
    }
    float rs = red[0];
    float inv = rs > 0.0f ? 1.0f / rs : 0.0f;
    g_anorm[(size_t)b * 65536 + i * 256 + t] = v * inv;
}

// -------------------- HMMA bf16x3 GEMM, cp.async 2-stage --------------------
// C[M,N] = A[M,K] @ B^T[N,K] (+bias, optional relu), fp32 via hi/lo bf16.
// Tile: BM=128, BN=128, BK=32. 256 threads, 8 warps = 2(M) x 4(N), warp 64x32.
// Smem rows skewed to 80B stride -> conflict-free ldmatrix/cp.async.
// 2 stages = 80KB -> 2 CTAs/SM (R10's 4-stage 160KB halved occupancy).
// CONV=true: A is im2col of x[12][512][2048]; chunk kt -> tap = kt>>11.
#define MM_STAGE 40960                       // 4 regions * 128 rows * 80B
#define MM_SMEM  (2 * MM_STAGE)              // 80 KB
#define OA_L 10240
#define OB_H 20480
#define OB_L 30720

template <bool CONV>
__global__ void __launch_bounds__(256, 2)
mma_gemm(const __nv_bfloat16* __restrict__ Ah, const __nv_bfloat16* __restrict__ Al,
         const __nv_bfloat16* __restrict__ Bh, const __nv_bfloat16* __restrict__ Bl,
         float* __restrict__ C, const float* __restrict__ bias, int relu,
         int K, int N)
{
    extern __shared__ __align__(128) char smem[];
    const uint32_t sbase = smem_u32(smem);
    const int tid  = threadIdx.x;
    const int lane = tid & 31;
    const int wid  = tid >> 5;
    const int bm = blockIdx.y * 128;
    const int bn = blockIdx.x * 128;
    const int wm = (wid & 1) * 64;
    const int wn = (wid >> 1) * 32;
    const int nch = K >> 5;

    uint32_t aoff[4];
#pragma unroll
    for (int mt = 0; mt < 4; mt++)
        aoff[mt] = (uint32_t)(wm + mt * 16 + (lane & 15)) * 80 + ((lane >> 4) * 16);
    const uint32_t boff = (uint32_t)(wn + lane) * 80;

    float acc[4][4][4];
#pragma unroll
    for (int i = 0; i < 4; i++)
#pragma unroll
        for (int j = 0; j < 4; j++)
#pragma unroll
            for (int r = 0; r < 4; r++) acc[i][j][r] = 0.0f;

    // per-thread loader geometry (8 x 16B cp.async per stage)
    const int l_r0 = tid >> 2;                // rows r0, r0+64
    const int l_cq = tid & 3;                 // 16B segment 0..3
    const uint32_t l_soff = (uint32_t)l_r0 * 80 + l_cq * 16;

    auto issue_stage = [&](int c, int slot) {
        const int kt = c << 5;
        const uint32_t sbs = sbase + slot * MM_STAGE;
        int tap = 0, ci0 = 0;
        if (CONV) { tap = kt >> 11; ci0 = kt & 2047; }
#pragma unroll
        for (int it = 0; it < 2; it++) {
            int row = l_r0 + it * 64;
            int cb = l_cq * 8;
            uint32_t off = l_soff + (uint32_t)it * (64 * 80);
            uint32_t asz = 16;
            size_t go;
            if (CONV) {
                int m = bm + row;
                int b = m >> 9;
                int t = (m & 511) - 1 + tap;
                bool ok = ((unsigned)t < 512u);
                go = ((size_t)b * 512 + (ok ? t : 0)) * 2048 + ci0 + cb;
                asz = ok ? 16u : 0u;
            } else {
                go = (size_t)(bm + row) * K + kt + cb;
            }
            size_t gb = (size_t)(bn + row) * K + kt + cb;
            cp16(sbs + off,        Ah + go, asz);
            cp16(sbs + OA_L + off, Al + go, asz);
            cp16(sbs + OB_H + off, Bh + gb, 16u);
            cp16(sbs + OB_L + off, Bl + gb, 16u);
        }
    };

    auto compute = [&](int buf) {
        uint32_t sb = sbase + buf * MM_STAGE;
#pragma unroll
        for (int h = 0; h < 2; h++) {
            uint32_t hb = (uint32_t)h * 32;
            uint32_t fah[4][4], fal[4][4], fbh[4][2], fbl[4][2];
#pragma unroll
            for (int mt = 0; mt < 4; mt++) {
                ldsm4(fah[mt][0], fah[mt][1], fah[mt][2], fah[mt][3],
                      sb + aoff[mt] + hb);
                ldsm4(fal[mt][0], fal[mt][1], fal[mt][2], fal[mt][3],
                      sb + OA_L + aoff[mt] + hb);
            }
            ldsm4(fbh[0][0], fbh[1][0], fbh[2][0], fbh[3][0], sb + OB_H + boff + hb);
            ldsm4(fbh[0][1], fbh[1][1], fbh[2][1], fbh[3][1], sb + OB_H + boff + hb + 16);
            ldsm4(fbl[0][0], fbl[1][0], fbl[2][0], fbl[3][0], sb + OB_L + boff + hb);
            ldsm4(fbl[0][1], fbl[1][1], fbl[2][1], fbl[3][1], sb + OB_L + boff + hb + 16);
#pragma unroll
            for (int mt = 0; mt < 4; mt++)
#pragma unroll
                for (int nt = 0; nt < 4; nt++) {
                    mma16816(acc[mt][nt], fah[mt], fbh[nt]);   // hi*hi
                    mma16816(acc[mt][nt], fah[mt], fbl[nt]);   // hi*lo
                    mma16816(acc[mt][nt], fal[mt], fbh[nt]);   // lo*hi
                }
        }
    };

    // 2-stage pipeline, depth-1 prefetch, one barrier per chunk:
    //   wait own cp.async -> barrier (cross-thread visibility; also proves all
    //   warps finished reading buf (c+1)&1 in compute(c-1)) -> issue c+1 into
    //   that buffer -> compute c.
    issue_stage(0, 0);
    CP_COMMIT();
    for (int c = 0; c < nch; c++) {
        CP_WAIT0();
        __syncthreads();
        if (c + 1 < nch) { issue_stage(c + 1, (c + 1) & 1); CP_COMMIT(); }
        compute(c & 1);
    }

    // epilogue: c0,c1 -> (row, col..col+1); c2,c3 -> (row+8, ...)
    const int r0 = lane >> 2, cp = (lane & 3) * 2;
#pragma unroll
    for (int mt = 0; mt < 4; mt++) {
        int row = bm + wm + mt * 16 + r0;
#pragma unroll
        for (int nt = 0; nt < 4; nt++) {
            int col = bn + wn + nt * 8 + cp;
            float b0 = bias ? __ldg(bias + col) : 0.0f;
            float b1 = bias ? __ldg(bias + col + 1) : 0.0f;
            float o0 = acc[mt][nt][0] + b0, o1 = acc[mt][nt][1] + b1;
            float o2 = acc[mt][nt][2] + b0, o3 = acc[mt][nt][3] + b1;
            if (relu) {
                o0 = fmaxf(o0, 0.f); o1 = fmaxf(o1, 0.f);
                o2 = fmaxf(o2, 0.f); o3 = fmaxf(o3, 0.f);
            }
            *(float2*)(C + (size_t)row * N + col)       = make_float2(o0, o1);
            *(float2*)(C + (size_t)(row + 8) * N + col) = make_float2(o2, o3);
        }
    }
}

// -------------------- FFMA2 GEMM (small batched a@H) ------------------------
#define BM 128
#define BN 128
#define BK 16
#define APAD 4

__device__ __forceinline__ ull pack2(float lo, float hi) {
    ull r; asm("mov.b64 %0, {%1, %2};" : "=l"(r) : "f"(lo), "f"(hi)); return r;
}
__device__ __forceinline__ void fma2(ull& d, ull a, ull b) {
    asm("fma.rn.f32x2 %0, %1, %2, %0;" : "+l"(d) : "l"(a), "l"(b));
}
__device__ __forceinline__ float2 unpack2(ull v) {
    float2 f; asm("mov.b64 {%0, %1}, %2;" : "=f"(f.x), "=f"(f.y) : "l"(v)); return f;
}

__global__ void __launch_bounds__(256, 2)
ffma_gemm(const float* __restrict__ A, size_t sA,
          const float* __restrict__ B, size_t sB,
          float* __restrict__ C, size_t sC,
          const float* __restrict__ bias, int do_relu,
          int M, int N, int K)
{
    A += (size_t)blockIdx.z * sA;
    B += (size_t)blockIdx.z * sB;
    C += (size_t)blockIdx.z * sC;
    const int bm = blockIdx.y * BM;
    const int bn = blockIdx.x * BN;

    __shared__ float As[2][BK][BM + APAD];
    __shared__ float Bs[2][BK][BN];

    const int tid = threadIdx.x;
    const int tx = tid & 15;
    const int ty = tid >> 4;
    const int a_r = tid >> 2;
    const int a_c = (tid & 3) * 4;
    const int b_r = tid >> 5;
    const int b_c = (tid & 31) * 4;

    ull acc[8][4];
#pragma unroll
    for (int i = 0; i < 8; i++)
#pragma unroll
        for (int j = 0; j < 4; j++) acc[i][j] = 0ull;

    float4 ra0, ra1, rb0, rb1;

    auto load_tiles = [&](int kt) {
        ra0 = *(const float4*)(A + (size_t)(bm + a_r) * K + kt + a_c);
        ra1 = *(const float4*)(A + (size_t)(bm + a_r + 64) * K + kt + a_c);
        rb0 = *(const float4*)(B + (size_t)(kt + b_r) * N + bn + b_c);
        rb1 = *(const float4*)(B + (size_t)(kt + b_r + 8) * N + bn + b_c);
    };
    auto store_tiles = [&](int buf) {
        As[buf][a_c + 0][a_r] = ra0.x; As[buf][a_c + 1][a_r] = ra0.y;
        As[buf][a_c + 2][a_r] = ra0.z; As[buf][a_c + 3][a_r] = ra0.w;
        As[buf][a_c + 0][a_r + 64] = ra1.x; As[buf][a_c + 1][a_r + 64] = ra1.y;
        As[buf][a_c + 2][a_r + 64] = ra1.z; As[buf][a_c + 3][a_r + 64] = ra1.w;
        *(float4*)&Bs[buf][b_r][b_c] = rb0;
        *(float4*)&Bs[buf][b_r + 8][b_c] = rb1;
    };
    auto compute = [&](int buf) {
#pragma unroll
        for (int k = 0; k < BK; k++) {
            float4 a0 = *(const float4*)&As[buf][k][ty * 8];
            float4 a1 = *(const float4*)&As[buf][k][ty * 8 + 4];
            float4 b0 = *(const float4*)&Bs[buf][k][tx * 8];
            float4 b1 = *(const float4*)&Bs[buf][k][tx * 8 + 4];
            ull bp0 = pack2(b0.x, b0.y), bp1 = pack2(b0.z, b0.w);
            ull bp2 = pack2(b1.x, b1.y), bp3 = pack2(b1.z, b1.w);
            float av[8] = {a0.x, a0.y, a0.z, a0.w, a1.x, a1.y, a1.z, a1.w};
#pragma unroll
            for (int i = 0; i < 8; i++) {
                ull ap = pack2(av[i], av[i]);
                fma2(acc[i][0], ap, bp0); fma2(acc[i][1], ap, bp1);
                fma2(acc[i][2], ap, bp2); fma2(acc[i][3], ap, bp3);
            }
        }
    };

    load_tiles(0);
    store_tiles(0);
    __syncthreads();
    int buf = 0;
    for (int kt = BK;; kt += BK) {
        bool more = kt < K;
        if (more) load_tiles(kt);
        compute(buf);
        if (!more) break;
        store_tiles(buf ^ 1);
        __syncthreads();
        buf ^= 1;
    }

    float bv[8];
#pragma unroll
    for (int j = 0; j < 8; j++) bv[j] = bias ? bias[bn + tx * 8 + j] : 0.0f;

#pragma unroll
    for (int i = 0; i < 8; i++) {
        float o[8];
        float2 p;
        p = unpack2(acc[i][0]); o[0] = p.x + bv[0]; o[1] = p.y + bv[1];
        p = unpack2(acc[i][1]); o[2] = p.x + bv[2]; o[3] = p.y + bv[3];
        p = unpack2(acc[i][2]); o[4] = p.x + bv[4]; o[5] = p.y + bv[5];
        p = unpack2(acc[i][3]); o[6] = p.x + bv[6]; o[7] = p.y + bv[7];
        if (do_relu) {
#pragma unroll
            for (int j = 0; j < 8; j++) o[j] = fmaxf(o[j], 0.0f);
        }
        size_t off = (size_t)(bm + ty * 8 + i) * N + bn + tx * 8;
        *(float4*)(C + off)     = make_float4(o[0], o[1], o[2], o[3]);
        *(float4*)(C + off + 4) = make_float4(o[4], o[5], o[6], o[7]);
    }
}

// ---------------------------------------------------------------------------
extern "C" void kernel_launch(void* const* d_in, const int* in_sizes, int n_in,
                              void* d_out, int out_size) {
    const float* x      = (const float*)d_in[0];
    const float* nodes  = (const float*)d_in[1];
    const float* adj    = (const float*)d_in[2];
    const float* conv_w = (const float*)d_in[3];
    const float* conv_b = (const float*)d_in[4];
    const float* W1     = (const float*)d_in[5];
    const float* b1     = (const float*)d_in[6];
    const float* W2     = (const float*)d_in[7];
    const float* b2     = (const float*)d_in[8];

    float* feats   = (float*)d_out;
    float* gcn_out = (float*)d_out + (size_t)12 * 512 * 2048;

    __nv_bfloat16 *xh, *xl, *wth, *wtl, *w1h, *w1l, *w2h, *w2l, *nh, *nl, *hh, *hl;
    float *anorm, *h1, *h2;
    cudaGetSymbolAddress((void**)&xh, g_xh);   cudaGetSymbolAddress((void**)&xl, g_xl);
    cudaGetSymbolAddress((void**)&wth, g_wth); cudaGetSymbolAddress((void**)&wtl, g_wtl);
    cudaGetSymbolAddress((void**)&w1h, g_w1h); cudaGetSymbolAddress((void**)&w1l, g_w1l);
    cudaGetSymbolAddress((void**)&w2h, g_w2h); cudaGetSymbolAddress((void**)&w2l, g_w2l);
    cudaGetSymbolAddress((void**)&nh, g_nh);   cudaGetSymbolAddress((void**)&nl, g_nl);
    cudaGetSymbolAddress((void**)&hh, g_hh);   cudaGetSymbolAddress((void**)&hl, g_hl);
    cudaGetSymbolAddress((void**)&anorm, g_anorm);
    cudaGetSymbolAddress((void**)&h1, g_h1);   cudaGetSymbolAddress((void**)&h2, g_h2);

    cudaFuncSetAttribute((const void*)mma_gemm<true>,
                         cudaFuncAttributeMaxDynamicSharedMemorySize, MM_SMEM);
    cudaFuncSetAttribute((const void*)mma_gemm<false>,
                         cudaFuncAttributeMaxDynamicSharedMemorySize, MM_SMEM);

    const bool fork = (g_s2 != nullptr) && (g_ev_fork != nullptr) && (g_ev_join != nullptr);
    cudaStream_t sB = fork ? g_s2 : (cudaStream_t)0;

    // fork branch B (GCN chain) off the capture stream before any work
    if (fork) {
        cudaEventRecord(g_ev_fork, 0);
        cudaStreamWaitEvent(g_s2, g_ev_fork, 0);
    }

    // --- branch A (conv path, capture stream); conv = 4th kernel issued ---
    convw_split_kernel<<<2048, 256>>>(conv_w);                       // (0)
    split_kernel<<<4096, 256>>>(x, xh, xl, 12 * 512 * 2048);         // (1)
    norm_adj_kernel<<<1024, 256, 0, sB>>>(adj);                      // (2, branch B)
    mma_gemm<true><<<dim3(16, 48), 256, MM_SMEM>>>(                  // (3) <- profiled
        xh, xl, wth, wtl, feats, conv_b, 1, 6144, 2048);

    // --- branch B (GCN chain), independent of conv ---
    transw_split_kernel<<<dim3(64, 64), dim3(32, 8), 0, sB>>>(W1, w1h, w1l);
    transw_split_kernel<<<dim3(64, 64), dim3(32, 8), 0, sB>>>(W2, w2h, w2l);
    split_kernel<<<2048, 256, 0, sB>>>(nodes, nh, nl, 1024 * 2048);
    mma_gemm<false><<<dim3(16, 8), 256, MM_SMEM, sB>>>(
        nh, nl, w1h, w1l, h1, nullptr, 0, 2048, 2048);
    ffma_gemm<<<dim3(16, 2, 4), 256, 0, sB>>>(
        anorm, 65536, h1, 524288, h2, 524288, b1, 1, 256, 2048, 256);
    split_kernel<<<2048, 256, 0, sB>>>(h2, hh, hl, 1024 * 2048);
    mma_gemm<false><<<dim3(16, 8), 256, MM_SMEM, sB>>>(
        hh, hl, w2h, w2l, h1, nullptr, 0, 2048, 2048);
    ffma_gemm<<<dim3(16, 2, 4), 256, 0, sB>>>(
        anorm, 65536, h1, 524288, gcn_out, 524288, b2, 0, 256, 2048, 256);

    // join branch B back into the capture stream
    if (fork) {
        cudaEventRecord(g_ev_join, g_s2);
        cudaStreamWaitEvent((cudaStream_t)0, g_ev_join, 0);
    }

    (void)in_sizes; (void)n_in; (void)out_size;
}

// round 14
// speedup vs baseline: 2.1578x; 1.3159x over previous
#include <cuda_runtime.h>
#include <cuda_bf16.h>
#include <cuda_fp16.h>
#include <cstdint>

// ===========================================================================
// GCN_81776177316393 — R12: conv on fp16 2-term HMMA (A=hi+lo, B=hi; 2 MMAs
// per k16 instead of 3 — the mma.sync issue-rate ceiling (~46% tensor at both
// 1 and 2 CTA/SM in R10/R11) means instruction COUNT is the only lever left).
// GCN chain stays bf16x3 + exact FFMA2, overlapped on a forked stream.
//   feats = relu(conv1d(x, conv_w, pad=1)) : [4,3,512,2048]
//   out   = a @ relu(a @ (nodes@W1) + b1) @ W2 + b2
// ===========================================================================

typedef unsigned long long ull;

// -------------------- scratch (static device globals) ----------------------
__device__ __align__(16) __half g_xh16[12u * 512u * 2048u];     // x hi (fp16)
__device__ __align__(16) __half g_xl16[12u * 512u * 2048u];     // x lo (fp16)
__device__ __align__(16) __half g_wh16[2048u * 6144u];          // convW^T hi: [co][tap*2048+ci]
__device__ __align__(16) __nv_bfloat16 g_w1h[2048u * 2048u];    // W1^T hi/lo (bf16)
__device__ __align__(16) __nv_bfloat16 g_w1l[2048u * 2048u];
__device__ __align__(16) __nv_bfloat16 g_w2h[2048u * 2048u];
__device__ __align__(16) __nv_bfloat16 g_w2l[2048u * 2048u];
__device__ __align__(16) __nv_bfloat16 g_nh[1024u * 2048u];
__device__ __align__(16) __nv_bfloat16 g_nl[1024u * 2048u];
__device__ __align__(16) __nv_bfloat16 g_hh[1024u * 2048u];
__device__ __align__(16) __nv_bfloat16 g_hl[1024u * 2048u];
__device__ float g_anorm[4 * 256 * 256];
__device__ float g_h1[1024u * 2048u];
__device__ float g_h2[1024u * 2048u];

// -------------------- pre-created stream/events (module load, pre-capture) --
static cudaStream_t g_s2 = nullptr;
static cudaEvent_t g_ev_fork = nullptr, g_ev_join = nullptr;
namespace {
struct StreamInit {
    StreamInit() {
        if (cudaStreamCreateWithFlags(&g_s2, cudaStreamNonBlocking) != cudaSuccess)
            g_s2 = nullptr;
        if (cudaEventCreateWithFlags(&g_ev_fork, cudaEventDisableTiming) != cudaSuccess)
            g_ev_fork = nullptr;
        if (cudaEventCreateWithFlags(&g_ev_join, cudaEventDisableTiming) != cudaSuccess)
            g_ev_join = nullptr;
    }
};
StreamInit g_stream_init;
}

// -------------------- PTX helpers ------------------------------------------
__device__ __forceinline__ uint32_t smem_u32(const void* p) {
    uint32_t a;
    asm("{ .reg .u64 t; cvta.to.shared.u64 t, %1; cvt.u32.u64 %0, t; }"
        : "=r"(a) : "l"(p));
    return a;
}
__device__ __forceinline__ void ldsm4(uint32_t& r0, uint32_t& r1,
                                      uint32_t& r2, uint32_t& r3, uint32_t addr) {
    asm volatile("ldmatrix.sync.aligned.m8n8.x4.shared.b16 {%0,%1,%2,%3}, [%4];"
                 : "=r"(r0), "=r"(r1), "=r"(r2), "=r"(r3) : "r"(addr));
}
__device__ __forceinline__ void mma_bf16(float* d, const uint32_t* a, const uint32_t* b) {
    asm volatile("mma.sync.aligned.m16n8k16.row.col.f32.bf16.bf16.f32 "
                 "{%0,%1,%2,%3}, {%4,%5,%6,%7}, {%8,%9}, {%0,%1,%2,%3};"
                 : "+f"(d[0]), "+f"(d[1]), "+f"(d[2]), "+f"(d[3])
                 : "r"(a[0]), "r"(a[1]), "r"(a[2]), "r"(a[3]), "r"(b[0]), "r"(b[1]));
}
__device__ __forceinline__ void mma_f16(float* d, const uint32_t* a, const uint32_t* b) {
    asm volatile("mma.sync.aligned.m16n8k16.row.col.f32.f16.f16.f32 "
                 "{%0,%1,%2,%3}, {%4,%5,%6,%7}, {%8,%9}, {%0,%1,%2,%3};"
                 : "+f"(d[0]), "+f"(d[1]), "+f"(d[2]), "+f"(d[3])
                 : "r"(a[0]), "r"(a[1]), "r"(a[2]), "r"(a[3]), "r"(b[0]), "r"(b[1]));
}
// 16B async copy; src_size=0 -> zero-fill (conv halo padding)
__device__ __forceinline__ void cp16(uint32_t dst, const void* src, uint32_t sz) {
    asm volatile("cp.async.cg.shared.global [%0], [%1], 16, %2;"
                 :: "r"(dst), "l"(src), "r"(sz) : "memory");
}
#define CP_COMMIT() asm volatile("cp.async.commit_group;" ::: "memory")
#define CP_WAIT0()  asm volatile("cp.async.wait_group 0;" ::: "memory")
#define CP_WAIT1()  asm volatile("cp.async.wait_group 1;" ::: "memory")

// -------------------- preprocessing kernels --------------------------------
// fp32 -> bf16 hi/lo (dense GCN path)
__global__ void split_kernel(const float* __restrict__ s, __nv_bfloat16* __restrict__ h,
                             __nv_bfloat16* __restrict__ l, int n) {
    int i = blockIdx.x * blockDim.x + threadIdx.x;
    int stride = gridDim.x * blockDim.x;
    for (; i < n; i += stride) {
        float v = s[i];
        __nv_bfloat16 hv = __float2bfloat16(v);
        h[i] = hv;
        l[i] = __float2bfloat16(v - __bfloat162float(hv));
    }
}
// fp32 -> fp16 hi/lo (conv activations)
__global__ void split_f16_kernel(const float* __restrict__ s, __half* __restrict__ h,
                                 __half* __restrict__ l, int n) {
    int i = blockIdx.x * blockDim.x + threadIdx.x;
    int stride = gridDim.x * blockDim.x;
    for (; i < n; i += stride) {
        float v = s[i];
        __half hv = __float2half_rn(v);
        h[i] = hv;
        l[i] = __float2half_rn(v - __half2float(hv));
    }
}
// conv_w[co][ci][tap] -> g_wh16[co][tap*2048+ci] (fp16 hi only)
__global__ void convw_f16_kernel(const float* __restrict__ w) {
    __shared__ float row[6144];
    int co = blockIdx.x;
    const float* src = w + (size_t)co * 6144;
    for (int j = threadIdx.x; j < 6144; j += 256) row[j] = src[j];
    __syncthreads();
    size_t base = (size_t)co * 6144;
    for (int kk = threadIdx.x; kk < 6144; kk += 256) {
        int tap = kk >> 11, ci = kk & 2047;
        g_wh16[base + kk] = __float2half_rn(row[ci * 3 + tap]);
    }
}
// W[k][n] -> out_hi/lo [n][k]  (bf16, dense path)
__global__ void transw_split_kernel(const float* __restrict__ W,
                                    __nv_bfloat16* __restrict__ oh,
                                    __nv_bfloat16* __restrict__ ol) {
    __shared__ float tile[32][33];
    int n0 = blockIdx.x * 32, k0 = blockIdx.y * 32;
    int tx = threadIdx.x, ty = threadIdx.y;
#pragma unroll
    for (int yy = 0; yy < 4; yy++)
        tile[ty + yy * 8][tx] = W[(size_t)(k0 + ty + yy * 8) * 2048 + n0 + tx];
    __syncthreads();
#pragma unroll
    for (int yy = 0; yy < 4; yy++) {
        float v = tile[tx][ty + yy * 8];
        size_t o = (size_t)(n0 + ty + yy * 8) * 2048 + k0 + tx;
        __nv_bfloat16 hv = __float2bfloat16(v);
        oh[o] = hv;
        ol[o] = __float2bfloat16(v - __bfloat162float(hv));
    }
}
// a = max(adj, adj^T) + I, row-normalized
__global__ void norm_adj_kernel(const float* __restrict__ adj) {
    int b = blockIdx.x >> 8;
    int i = blockIdx.x & 255;
    int t = threadIdx.x;
    const float* ab = adj + (size_t)b * 65536;
    float v = fmaxf(ab[i * 256 + t], ab[t * 256 + i]) + (t == i ? 1.0f : 0.0f);
    __shared__ float red[256];
    red[t] = v;
    __syncthreads();
#pragma unroll
    for (int s = 128; s > 0; s >>= 1) {
        if (t < s) red[t] += red[t + s];
        __syncthreads();
    }
    float rs = red[0];
    float inv = rs > 0.0f ? 1.0f / rs : 0.0f;
    g_anorm[(size_t)b * 65536 + i * 256 + t] = v * inv;
}

// -------------------- conv GEMM: fp16 2-term, 3-stage cp.async --------------
// feats[M,N] = relu(imcol(x)[M,K] @ Wt[N,K] + bias), M=6144, N=2048, K=6144.
// C = Ah@Bh + Al@Bh (dropped Ah@Bl term: ~2^-12 rel err). 2 MMAs per k16.
// Stage = A_hi 10K + A_lo 10K + B_hi 10K = 30KB; 3 stages = 90KB, 2 CTA/SM.
#define CV_STAGE 30720
#define CV_SMEM  (3 * CV_STAGE)
#define CV_AL 10240
#define CV_BH 20480

__global__ void __launch_bounds__(256, 2)
conv_gemm(const __half* __restrict__ Ah, const __half* __restrict__ Al,
          const __half* __restrict__ Bh, float* __restrict__ C,
          const float* __restrict__ bias, int K, int N)
{
    extern __shared__ __align__(128) char smem[];
    const uint32_t sbase = smem_u32(smem);
    const int tid  = threadIdx.x;
    const int lane = tid & 31;
    const int wid  = tid >> 5;
    const int bm = blockIdx.y * 128;
    const int bn = blockIdx.x * 128;
    const int wm = (wid & 1) * 64;
    const int wn = (wid >> 1) * 32;
    const int nch = K >> 5;

    uint32_t aoff[4];
#pragma unroll
    for (int mt = 0; mt < 4; mt++)
        aoff[mt] = (uint32_t)(wm + mt * 16 + (lane & 15)) * 80 + ((lane >> 4) * 16);
    const uint32_t boff = (uint32_t)(wn + lane) * 80;

    float acc[4][4][4];
#pragma unroll
    for (int i = 0; i < 4; i++)
#pragma unroll
        for (int j = 0; j < 4; j++)
#pragma unroll
            for (int r = 0; r < 4; r++) acc[i][j][r] = 0.0f;

    const int l_r0 = tid >> 2;
    const int l_cq = tid & 3;
    const uint32_t l_soff = (uint32_t)l_r0 * 80 + l_cq * 16;

    auto issue_stage = [&](int c, int slot) {
        const int kt = c << 5;
        const uint32_t sbs = sbase + slot * CV_STAGE;
        const int tap = kt >> 11, ci0 = kt & 2047;
#pragma unroll
        for (int it = 0; it < 2; it++) {
            int row = l_r0 + it * 64;
            int cb = l_cq * 8;
            uint32_t off = l_soff + (uint32_t)it * (64 * 80);
            int m = bm + row;
            int b = m >> 9;
            int t = (m & 511) - 1 + tap;
            bool ok = ((unsigned)t < 512u);
            size_t go = ((size_t)b * 512 + (ok ? t : 0)) * 2048 + ci0 + cb;
            uint32_t asz = ok ? 16u : 0u;
            size_t gb = (size_t)(bn + row) * K + kt + cb;
            cp16(sbs + off,         Ah + go, asz);
            cp16(sbs + CV_AL + off, Al + go, asz);
            cp16(sbs + CV_BH + off, Bh + gb, 16u);
        }
    };

    auto compute = [&](int buf) {
        uint32_t sb = sbase + buf * CV_STAGE;
#pragma unroll
        for (int h = 0; h < 2; h++) {
            uint32_t hb = (uint32_t)h * 32;
            uint32_t fah[4][4], fal[4][4], fbh[4][2];
#pragma unroll
            for (int mt = 0; mt < 4; mt++) {
                ldsm4(fah[mt][0], fah[mt][1], fah[mt][2], fah[mt][3],
                      sb + aoff[mt] + hb);
                ldsm4(fal[mt][0], fal[mt][1], fal[mt][2], fal[mt][3],
                      sb + CV_AL + aoff[mt] + hb);
            }
            ldsm4(fbh[0][0], fbh[1][0], fbh[2][0], fbh[3][0], sb + CV_BH + boff + hb);
            ldsm4(fbh[0][1], fbh[1][1], fbh[2][1], fbh[3][1], sb + CV_BH + boff + hb + 16);
#pragma unroll
            for (int mt = 0; mt < 4; mt++)
#pragma unroll
                for (int nt = 0; nt < 4; nt++) {
                    mma_f16(acc[mt][nt], fah[mt], fbh[nt]);   // hi * hi
                    mma_f16(acc[mt][nt], fal[mt], fbh[nt]);   // lo * hi
                }
        }
    };

    // 3-stage pipeline, depth-2 prefetch; one (possibly empty) commit per iter
    // keeps the wait_group accounting exact: at iter c, wait_group 1 leaves at
    // most the newest group in flight => stage c has landed.
    issue_stage(0, 0); CP_COMMIT();
    issue_stage(1, 1); CP_COMMIT();
    for (int c = 0; c < nch; c++) {
        CP_WAIT1();
        __syncthreads();           // stage c visible to all; buf (c+2)%3 drained
        if (c + 2 < nch) issue_stage(c + 2, (c + 2) % 3);
        CP_COMMIT();
        compute(c % 3);
    }

    const int r0 = lane >> 2, cp = (lane & 3) * 2;
#pragma unroll
    for (int mt = 0; mt < 4; mt++) {
        int row = bm + wm + mt * 16 + r0;
#pragma unroll
        for (int nt = 0; nt < 4; nt++) {
            int col = bn + wn + nt * 8 + cp;
            float b0 = __ldg(bias + col);
            float b1 = __ldg(bias + col + 1);
            float o0 = fmaxf(acc[mt][nt][0] + b0, 0.f);
            float o1 = fmaxf(acc[mt][nt][1] + b1, 0.f);
            float o2 = fmaxf(acc[mt][nt][2] + b0, 0.f);
            float o3 = fmaxf(acc[mt][nt][3] + b1, 0.f);
            *(float2*)(C + (size_t)row * N + col)       = make_float2(o0, o1);
            *(float2*)(C + (size_t)(row + 8) * N + col) = make_float2(o2, o3);
        }
    }
}

// -------------------- dense GEMM: bf16x3, 2-stage cp.async (R11-proven) ----
#define MM_STAGE 40960
#define MM_SMEM  (2 * MM_STAGE)
#define OA_L 10240
#define OB_H 20480
#define OB_L 30720

__global__ void __launch_bounds__(256, 2)
mma_gemm(const __nv_bfloat16* __restrict__ Ah, const __nv_bfloat16* __restrict__ Al,
         const __nv_bfloat16* __restrict__ Bh, const __nv_bfloat16* __restrict__ Bl,
         float* __restrict__ C, int K, int N)
{
    extern __shared__ __align__(128) char smem[];
    const uint32_t sbase = smem_u32(smem);
    const int tid  = threadIdx.x;
    const int lane = tid & 31;
    const int wid  = tid >> 5;
    const int bm = blockIdx.y * 128;
    const int bn = blockIdx.x * 128;
    const int wm = (wid & 1) * 64;
    const int wn = (wid >> 1) * 32;
    const int nch = K >> 5;

    uint32_t aoff[4];
#pragma unroll
    for (int mt = 0; mt < 4; mt++)
        aoff[mt] = (uint32_t)(wm + mt * 16 + (lane & 15)) * 80 + ((lane >> 4) * 16);
    const uint32_t boff = (uint32_t)(wn + lane) * 80;

    float acc[4][4][4];
#pragma unroll
    for (int i = 0; i < 4; i++)
#pragma unroll
        for (int j = 0; j < 4; j++)
#pragma unroll
            for (int r = 0; r < 4; r++) acc[i][j][r] = 0.0f;

    const int l_r0 = tid >> 2;
    const int l_cq = tid & 3;
    const uint32_t l_soff = (uint32_t)l_r0 * 80 + l_cq * 16;

    auto issue_stage = [&](int c, int slot) {
        const int kt = c << 5;
        const uint32_t sbs = sbase + slot * MM_STAGE;
#pragma unroll
        for (int it = 0; it < 2; it++) {
            int row = l_r0 + it * 64;
            int cb = l_cq * 8;
            uint32_t off = l_soff + (uint32_t)it * (64 * 80);
            size_t go = (size_t)(bm + row) * K + kt + cb;
            size_t gb = (size_t)(bn + row) * K + kt + cb;
            cp16(sbs + off,        Ah + go, 16u);
            cp16(sbs + OA_L + off, Al + go, 16u);
            cp16(sbs + OB_H + off, Bh + gb, 16u);
            cp16(sbs + OB_L + off, Bl + gb, 16u);
        }
    };

    auto compute = [&](int buf) {
        uint32_t sb = sbase + buf * MM_STAGE;
#pragma unroll
        for (int h = 0; h < 2; h++) {
            uint32_t hb = (uint32_t)h * 32;
            uint32_t fah[4][4], fal[4][4], fbh[4][2], fbl[4][2];
#pragma unroll
            for (int mt = 0; mt < 4; mt++) {
                ldsm4(fah[mt][0], fah[mt][1], fah[mt][2], fah[mt][3],
                      sb + aoff[mt] + hb);
                ldsm4(fal[mt][0], fal[mt][1], fal[mt][2], fal[mt][3],
                      sb + OA_L + aoff[mt] + hb);
            }
            ldsm4(fbh[0][0], fbh[1][0], fbh[2][0], fbh[3][0], sb + OB_H + boff + hb);
            ldsm4(fbh[0][1], fbh[1][1], fbh[2][1], fbh[3][1], sb + OB_H + boff + hb + 16);
            ldsm4(fbl[0][0], fbl[1][0], fbl[2][0], fbl[3][0], sb + OB_L + boff + hb);
            ldsm4(fbl[0][1], fbl[1][1], fbl[2][1], fbl[3][1], sb + OB_L + boff + hb + 16);
#pragma unroll
            for (int mt = 0; mt < 4; mt++)
#pragma unroll
                for (int nt = 0; nt < 4; nt++) {
                    mma_bf16(acc[mt][nt], fah[mt], fbh[nt]);
                    mma_bf16(acc[mt][nt], fah[mt], fbl[nt]);
                    mma_bf16(acc[mt][nt], fal[mt], fbh[nt]);
                }
        }
    };

    issue_stage(0, 0);
    CP_COMMIT();
    for (int c = 0; c < nch; c++) {
        CP_WAIT0();
        __syncthreads();
        if (c + 1 < nch) { issue_stage(c + 1, (c + 1) & 1); CP_COMMIT(); }
        compute(c & 1);
    }

    const int r0 = lane >> 2, cp = (lane & 3) * 2;
#pragma unroll
    for (int mt = 0; mt < 4; mt++) {
        int row = bm + wm + mt * 16 + r0;
#pragma unroll
        for (int nt = 0; nt < 4; nt++) {
            int col = bn + wn + nt * 8 + cp;
            *(float2*)(C + (size_t)row * N + col) =
                make_float2(acc[mt][nt][0], acc[mt][nt][1]);
            *(float2*)(C + (size_t)(row + 8) * N + col) =
                make_float2(acc[mt][nt][2], acc[mt][nt][3]);
        }
    }
}

// -------------------- FFMA2 GEMM (small batched a@H, exact fp32) ------------
#define BM 128
#define BN 128
#define BK 16
#define APAD 4

__device__ __forceinline__ ull pack2(float lo, float hi) {
    ull r; asm("mov.b64 %0, {%1, %2};" : "=l"(r) : "f"(lo), "f"(hi)); return r;
}
__device__ __forceinline__ void fma2(ull& d, ull a, ull b) {
    asm("fma.rn.f32x2 %0, %1, %2, %0;" : "+l"(d) : "l"(a), "l"(b));
}
__device__ __forceinline__ float2 unpack2(ull v) {
    float2 f; asm("mov.b64 {%0, %1}, %2;" : "=f"(f.x), "=f"(f.y) : "l"(v)); return f;
}

__global__ void __launch_bounds__(256, 2)
ffma_gemm(const float* __restrict__ A, size_t sA,
          const float* __restrict__ B, size_t sB,
          float* __restrict__ C, size_t sC,
          const float* __restrict__ bias, int do_relu,
          int M, int N, int K)
{
    A += (size_t)blockIdx.z * sA;
    B += (size_t)blockIdx.z * sB;
    C += (size_t)blockIdx.z * sC;
    const int bm = blockIdx.y * BM;
    const int bn = blockIdx.x * BN;

    __shared__ float As[2][BK][BM + APAD];
    __shared__ float Bs[2][BK][BN];

    const int tid = threadIdx.x;
    const int tx = tid & 15;
    const int ty = tid >> 4;
    const int a_r = tid >> 2;
    const int a_c = (tid & 3) * 4;
    const int b_r = tid >> 5;
    const int b_c = (tid & 31) * 4;

    ull acc[8][4];
#pragma unroll
    for (int i = 0; i < 8; i++)
#pragma unroll
        for (int j = 0; j < 4; j++) acc[i][j] = 0ull;

    float4 ra0, ra1, rb0, rb1;

    auto load_tiles = [&](int kt) {
        ra0 = *(const float4*)(A + (size_t)(bm + a_r) * K + kt + a_c);
        ra1 = *(const float4*)(A + (size_t)(bm + a_r + 64) * K + kt + a_c);
        rb0 = *(const float4*)(B + (size_t)(kt + b_r) * N + bn + b_c);
        rb1 = *(const float4*)(B + (size_t)(kt + b_r + 8) * N + bn + b_c);
    };
    auto store_tiles = [&](int buf) {
        As[buf][a_c + 0][a_r] = ra0.x; As[buf][a_c + 1][a_r] = ra0.y;
        As[buf][a_c + 2][a_r] = ra0.z; As[buf][a_c + 3][a_r] = ra0.w;
        As[buf][a_c + 0][a_r + 64] = ra1.x; As[buf][a_c + 1][a_r + 64] = ra1.y;
        As[buf][a_c + 2][a_r + 64] = ra1.z; As[buf][a_c + 3][a_r + 64] = ra1.w;
        *(float4*)&Bs[buf][b_r][b_c] = rb0;
        *(float4*)&Bs[buf][b_r + 8][b_c] = rb1;
    };
    auto compute = [&](int buf) {
#pragma unroll
        for (int k = 0; k < BK; k++) {
            float4 a0 = *(const float4*)&As[buf][k][ty * 8];
            float4 a1 = *(const float4*)&As[buf][k][ty * 8 + 4];
            float4 b0 = *(const float4*)&Bs[buf][k][tx * 8];
            float4 b1 = *(const float4*)&Bs[buf][k][tx * 8 + 4];
            ull bp0 = pack2(b0.x, b0.y), bp1 = pack2(b0.z, b0.w);
            ull bp2 = pack2(b1.x, b1.y), bp3 = pack2(b1.z, b1.w);
            float av[8] = {a0.x, a0.y, a0.z, a0.w, a1.x, a1.y, a1.z, a1.w};
#pragma unroll
            for (int i = 0; i < 8; i++) {
                ull ap = pack2(av[i], av[i]);
                fma2(acc[i][0], ap, bp0); fma2(acc[i][1], ap, bp1);
                fma2(acc[i][2], ap, bp2); fma2(acc[i][3], ap, bp3);
            }
        }
    };

    load_tiles(0);
    store_tiles(0);
    __syncthreads();
    int buf = 0;
    for (int kt = BK;; kt += BK) {
        bool more = kt < K;
        if (more) load_tiles(kt);
        compute(buf);
        if (!more) break;
        store_tiles(buf ^ 1);
        __syncthreads();
        buf ^= 1;
    }

    float bv[8];
#pragma unroll
    for (int j = 0; j < 8; j++) bv[j] = bias ? bias[bn + tx * 8 + j] : 0.0f;

#pragma unroll
    for (int i = 0; i < 8; i++) {
        float o[8];
        float2 p;
        p = unpack2(acc[i][0]); o[0] = p.x + bv[0]; o[1] = p.y + bv[1];
        p = unpack2(acc[i][1]); o[2] = p.x + bv[2]; o[3] = p.y + bv[3];
        p = unpack2(acc[i][2]); o[4] = p.x + bv[4]; o[5] = p.y + bv[5];
        p = unpack2(acc[i][3]); o[6] = p.x + bv[6]; o[7] = p.y + bv[7];
        if (do_relu) {
#pragma unroll
            for (int j = 0; j < 8; j++) o[j] = fmaxf(o[j], 0.0f);
        }
        size_t off = (size_t)(bm + ty * 8 + i) * N + bn + tx * 8;
        *(float4*)(C + off)     = make_float4(o[0], o[1], o[2], o[3]);
        *(float4*)(C + off + 4) = make_float4(o[4], o[5], o[6], o[7]);
    }
}

// ---------------------------------------------------------------------------
extern "C" void kernel_launch(void* const* d_in, const int* in_sizes, int n_in,
                              void* d_out, int out_size) {
    const float* x      = (const float*)d_in[0];
    const float* nodes  = (const float*)d_in[1];
    const float* adj    = (const float*)d_in[2];
    const float* conv_w = (const float*)d_in[3];
    const float* conv_b = (const float*)d_in[4];
    const float* W1     = (const float*)d_in[5];
    const float* b1     = (const float*)d_in[6];
    const float* W2     = (const float*)d_in[7];
    const float* b2     = (const float*)d_in[8];

    float* feats   = (float*)d_out;
    float* gcn_out = (float*)d_out + (size_t)12 * 512 * 2048;

    __half *xh, *xl, *wh;
    __nv_bfloat16 *w1h, *w1l, *w2h, *w2l, *nh, *nl, *hh, *hl;
    float *anorm, *h1, *h2;
    cudaGetSymbolAddress((void**)&xh, g_xh16);  cudaGetSymbolAddress((void**)&xl, g_xl16);
    cudaGetSymbolAddress((void**)&wh, g_wh16);
    cudaGetSymbolAddress((void**)&w1h, g_w1h);  cudaGetSymbolAddress((void**)&w1l, g_w1l);
    cudaGetSymbolAddress((void**)&w2h, g_w2h);  cudaGetSymbolAddress((void**)&w2l, g_w2l);
    cudaGetSymbolAddress((void**)&nh, g_nh);    cudaGetSymbolAddress((void**)&nl, g_nl);
    cudaGetSymbolAddress((void**)&hh, g_hh);    cudaGetSymbolAddress((void**)&hl, g_hl);
    cudaGetSymbolAddress((void**)&anorm, g_anorm);
    cudaGetSymbolAddress((void**)&h1, g_h1);    cudaGetSymbolAddress((void**)&h2, g_h2);

    cudaFuncSetAttribute((const void*)conv_gemm,
                         cudaFuncAttributeMaxDynamicSharedMemorySize, CV_SMEM);
    cudaFuncSetAttribute((const void*)mma_gemm,
                         cudaFuncAttributeMaxDynamicSharedMemorySize, MM_SMEM);

    const bool fork = (g_s2 != nullptr) && (g_ev_fork != nullptr) && (g_ev_join != nullptr);
    cudaStream_t sB = fork ? g_s2 : (cudaStream_t)0;

    if (fork) {
        cudaEventRecord(g_ev_fork, 0);
        cudaStreamWaitEvent(g_s2, g_ev_fork, 0);
    }

    // --- branch A (conv path, capture stream); conv = 4th kernel issued ---
    convw_f16_kernel<<<2048, 256>>>(conv_w);                         // (0)
    split_f16_kernel<<<4096, 256>>>(x, xh, xl, 12 * 512 * 2048);     // (1)
    norm_adj_kernel<<<1024, 256, 0, sB>>>(adj);                      // (2, branch B)
    conv_gemm<<<dim3(16, 48), 256, CV_SMEM>>>(                       // (3) <- profiled
        xh, xl, wh, feats, conv_b, 6144, 2048);

    // --- branch B (GCN chain), independent of conv, bf16x3 + exact ffma ---
    transw_split_kernel<<<dim3(64, 64), dim3(32, 8), 0, sB>>>(W1, w1h, w1l);
    transw_split_kernel<<<dim3(64, 64), dim3(32, 8), 0, sB>>>(W2, w2h, w2l);
    split_kernel<<<2048, 256, 0, sB>>>(nodes, nh, nl, 1024 * 2048);
    mma_gemm<<<dim3(16, 8), 256, MM_SMEM, sB>>>(
        nh, nl, w1h, w1l, h1, 2048, 2048);
    ffma_gemm<<<dim3(16, 2, 4), 256, 0, sB>>>(
        anorm, 65536, h1, 524288, h2, 524288, b1, 1, 256, 2048, 256);
    split_kernel<<<2048, 256, 0, sB>>>(h2, hh, hl, 1024 * 2048);
    mma_gemm<<<dim3(16, 8), 256, MM_SMEM, sB>>>(
        hh, hl, w2h, w2l, h1, 2048, 2048);
    ffma_gemm<<<dim3(16, 2, 4), 256, 0, sB>>>(
        anorm, 65536, h1, 524288, gcn_out, 524288, b2, 0, 256, 2048, 256);

    if (fork) {
        cudaEventRecord(g_ev_join, g_s2);
        cudaStreamWaitEvent((cudaStream_t)0, g_ev_join, 0);
    }

    (void)in_sizes; (void)n_in; (void)out_size;
}

// round 16
// speedup vs baseline: 2.9623x; 1.3728x over previous
#include <cuda_runtime.h>
#include <cuda_bf16.h>
#include <cuda_fp16.h>
#include <cstdint>

// ===========================================================================
// GCN_81776177316393 — R15: conv on PURE fp16 hi*hi HMMA (1 MMA per k16).
// Measured error anchor: R14's 2-term conv gave 2.08e-4 from the dropped
// ah*bl term; dropping al*bh adds an iid contribution -> ~3-4.2e-4, still
// 2.4-3x under the 1e-3 gate. mma.sync is instruction-count bound (tensor%
// pinned ~43-46% across occupancies in R10/R11/R14), so halving MMAs ~halves
// conv time. GCN chain stays bf16x3 + exact FFMA2 on a forked stream.
//   feats = relu(conv1d(x, conv_w, pad=1)) : [4,3,512,2048]
//   out   = a @ relu(a @ (nodes@W1) + b1) @ W2 + b2
// ===========================================================================

typedef unsigned long long ull;

// -------------------- scratch (static device globals) ----------------------
__device__ __align__(16) __half g_xh16[12u * 512u * 2048u];     // x hi (fp16)
__device__ __align__(16) __half g_wh16[2048u * 6144u];          // convW^T hi: [co][tap*2048+ci]
__device__ __align__(16) __nv_bfloat16 g_w1h[2048u * 2048u];    // W1^T hi/lo (bf16)
__device__ __align__(16) __nv_bfloat16 g_w1l[2048u * 2048u];
__device__ __align__(16) __nv_bfloat16 g_w2h[2048u * 2048u];
__device__ __align__(16) __nv_bfloat16 g_w2l[2048u * 2048u];
__device__ __align__(16) __nv_bfloat16 g_nh[1024u * 2048u];
__device__ __align__(16) __nv_bfloat16 g_nl[1024u * 2048u];
__device__ __align__(16) __nv_bfloat16 g_hh[1024u * 2048u];
__device__ __align__(16) __nv_bfloat16 g_hl[1024u * 2048u];
__device__ float g_anorm[4 * 256 * 256];
__device__ float g_h1[1024u * 2048u];
__device__ float g_h2[1024u * 2048u];

// -------------------- pre-created stream/events (module load, pre-capture) --
static cudaStream_t g_s2 = nullptr;
static cudaEvent_t g_ev_fork = nullptr, g_ev_join = nullptr;
namespace {
struct StreamInit {
    StreamInit() {
        if (cudaStreamCreateWithFlags(&g_s2, cudaStreamNonBlocking) != cudaSuccess)
            g_s2 = nullptr;
        if (cudaEventCreateWithFlags(&g_ev_fork, cudaEventDisableTiming) != cudaSuccess)
            g_ev_fork = nullptr;
        if (cudaEventCreateWithFlags(&g_ev_join, cudaEventDisableTiming) != cudaSuccess)
            g_ev_join = nullptr;
    }
};
StreamInit g_stream_init;
}

// -------------------- PTX helpers ------------------------------------------
__device__ __forceinline__ uint32_t smem_u32(const void* p) {
    uint32_t a;
    asm("{ .reg .u64 t; cvta.to.shared.u64 t, %1; cvt.u32.u64 %0, t; }"
        : "=r"(a) : "l"(p));
    return a;
}
__device__ __forceinline__ void ldsm4(uint32_t& r0, uint32_t& r1,
                                      uint32_t& r2, uint32_t& r3, uint32_t addr) {
    asm volatile("ldmatrix.sync.aligned.m8n8.x4.shared.b16 {%0,%1,%2,%3}, [%4];"
                 : "=r"(r0), "=r"(r1), "=r"(r2), "=r"(r3) : "r"(addr));
}
__device__ __forceinline__ void mma_bf16(float* d, const uint32_t* a, const uint32_t* b) {
    asm volatile("mma.sync.aligned.m16n8k16.row.col.f32.bf16.bf16.f32 "
                 "{%0,%1,%2,%3}, {%4,%5,%6,%7}, {%8,%9}, {%0,%1,%2,%3};"
                 : "+f"(d[0]), "+f"(d[1]), "+f"(d[2]), "+f"(d[3])
                 : "r"(a[0]), "r"(a[1]), "r"(a[2]), "r"(a[3]), "r"(b[0]), "r"(b[1]));
}
__device__ __forceinline__ void mma_f16(float* d, const uint32_t* a, const uint32_t* b) {
    asm volatile("mma.sync.aligned.m16n8k16.row.col.f32.f16.f16.f32 "
                 "{%0,%1,%2,%3}, {%4,%5,%6,%7}, {%8,%9}, {%0,%1,%2,%3};"
                 : "+f"(d[0]), "+f"(d[1]), "+f"(d[2]), "+f"(d[3])
                 : "r"(a[0]), "r"(a[1]), "r"(a[2]), "r"(a[3]), "r"(b[0]), "r"(b[1]));
}
// 16B async copy; src_size=0 -> zero-fill (conv halo padding)
__device__ __forceinline__ void cp16(uint32_t dst, const void* src, uint32_t sz) {
    asm volatile("cp.async.cg.shared.global [%0], [%1], 16, %2;"
                 :: "r"(dst), "l"(src), "r"(sz) : "memory");
}
#define CP_COMMIT() asm volatile("cp.async.commit_group;" ::: "memory")
#define CP_WAIT0()  asm volatile("cp.async.wait_group 0;" ::: "memory")
#define CP_WAIT1()  asm volatile("cp.async.wait_group 1;" ::: "memory")

// -------------------- preprocessing kernels --------------------------------
// fp32 -> bf16 hi/lo (dense GCN path)
__global__ void split_kernel(const float* __restrict__ s, __nv_bfloat16* __restrict__ h,
                             __nv_bfloat16* __restrict__ l, int n) {
    int i = blockIdx.x * blockDim.x + threadIdx.x;
    int stride = gridDim.x * blockDim.x;
    for (; i < n; i += stride) {
        float v = s[i];
        __nv_bfloat16 hv = __float2bfloat16(v);
        h[i] = hv;
        l[i] = __float2bfloat16(v - __bfloat162float(hv));
    }
}
// fp32 -> fp16 hi only (conv activations)
__global__ void cast_f16_kernel(const float* __restrict__ s, __half* __restrict__ h, int n) {
    int i = blockIdx.x * blockDim.x + threadIdx.x;
    int stride = gridDim.x * blockDim.x;
    for (; i < n; i += stride)
        h[i] = __float2half_rn(s[i]);
}
// conv_w[co][ci][tap] -> g_wh16[co][tap*2048+ci] (fp16 hi only)
__global__ void convw_f16_kernel(const float* __restrict__ w) {
    __shared__ float row[6144];
    int co = blockIdx.x;
    const float* src = w + (size_t)co * 6144;
    for (int j = threadIdx.x; j < 6144; j += 256) row[j] = src[j];
    __syncthreads();
    size_t base = (size_t)co * 6144;
    for (int kk = threadIdx.x; kk < 6144; kk += 256) {
        int tap = kk >> 11, ci = kk & 2047;
        g_wh16[base + kk] = __float2half_rn(row[ci * 3 + tap]);
    }
}
// W[k][n] -> out_hi/lo [n][k]  (bf16, dense path)
__global__ void transw_split_kernel(const float* __restrict__ W,
                                    __nv_bfloat16* __restrict__ oh,
                                    __nv_bfloat16* __restrict__ ol) {
    __shared__ float tile[32][33];
    int n0 = blockIdx.x * 32, k0 = blockIdx.y * 32;
    int tx = threadIdx.x, ty = threadIdx.y;
#pragma unroll
    for (int yy = 0; yy < 4; yy++)
        tile[ty + yy * 8][tx] = W[(size_t)(k0 + ty + yy * 8) * 2048 + n0 + tx];
    __syncthreads();
#pragma unroll
    for (int yy = 0; yy < 4; yy++) {
        float v = tile[tx][ty + yy * 8];
        size_t o = (size_t)(n0 + ty + yy * 8) * 2048 + k0 + tx;
        __nv_bfloat16 hv = __float2bfloat16(v);
        oh[o] = hv;
        ol[o] = __float2bfloat16(v - __bfloat162float(hv));
    }
}
// a = max(adj, adj^T) + I, row-normalized
__global__ void norm_adj_kernel(const float* __restrict__ adj) {
    int b = blockIdx.x >> 8;
    int i = blockIdx.x & 255;
    int t = threadIdx.x;
    const float* ab = adj + (size_t)b * 65536;
    float v = fmaxf(ab[i * 256 + t], ab[t * 256 + i]) + (t == i ? 1.0f : 0.0f);
    __shared__ float red[256];
    red[t] = v;
    __syncthreads();
#pragma unroll
    for (int s = 128; s > 0; s >>= 1) {
        if (t < s) red[t] += red[t + s];
        __syncthreads();
    }
    float rs = red[0];
    float inv = rs > 0.0f ? 1.0f / rs : 0.0f;
    g_anorm[(size_t)b * 65536 + i * 256 + t] = v * inv;
}

// -------------------- conv GEMM: pure fp16, 3-stage cp.async ----------------
// feats[M,N] = relu(imcol(x)[M,K] @ Wt[N,K] + bias), M=6144, N=2048, K=6144.
// C = Ah@Bh only (dropped lo terms; measured anchor R14 = 2.08e-4 with one
// lo term kept -> expected ~3-4.2e-4 here). 1 MMA per k16.
// Stage = A 10K + B 10K = 20KB; 3 stages = 60KB, 2 CTA/SM.
#define CV_STAGE 20480
#define CV_SMEM  (3 * CV_STAGE)
#define CV_BH 10240

__global__ void __launch_bounds__(256, 2)
conv_gemm(const __half* __restrict__ Ah, const __half* __restrict__ Bh,
          float* __restrict__ C, const float* __restrict__ bias, int K, int N)
{
    extern __shared__ __align__(128) char smem[];
    const uint32_t sbase = smem_u32(smem);
    const int tid  = threadIdx.x;
    const int lane = tid & 31;
    const int wid  = tid >> 5;
    const int bm = blockIdx.y * 128;
    const int bn = blockIdx.x * 128;
    const int wm = (wid & 1) * 64;
    const int wn = (wid >> 1) * 32;
    const int nch = K >> 5;

    uint32_t aoff[4];
#pragma unroll
    for (int mt = 0; mt < 4; mt++)
        aoff[mt] = (uint32_t)(wm + mt * 16 + (lane & 15)) * 80 + ((lane >> 4) * 16);
    const uint32_t boff = (uint32_t)(wn + lane) * 80;

    float acc[4][4][4];
#pragma unroll
    for (int i = 0; i < 4; i++)
#pragma unroll
        for (int j = 0; j < 4; j++)
#pragma unroll
            for (int r = 0; r < 4; r++) acc[i][j][r] = 0.0f;

    const int l_r0 = tid >> 2;
    const int l_cq = tid & 3;
    const uint32_t l_soff = (uint32_t)l_r0 * 80 + l_cq * 16;

    auto issue_stage = [&](int c, int slot) {
        const int kt = c << 5;
        const uint32_t sbs = sbase + slot * CV_STAGE;
        const int tap = kt >> 11, ci0 = kt & 2047;
#pragma unroll
        for (int it = 0; it < 2; it++) {
            int row = l_r0 + it * 64;
            int cb = l_cq * 8;
            uint32_t off = l_soff + (uint32_t)it * (64 * 80);
            int m = bm + row;
            int b = m >> 9;
            int t = (m & 511) - 1 + tap;
            bool ok = ((unsigned)t < 512u);
            size_t go = ((size_t)b * 512 + (ok ? t : 0)) * 2048 + ci0 + cb;
            uint32_t asz = ok ? 16u : 0u;
            size_t gb = (size_t)(bn + row) * K + kt + cb;
            cp16(sbs + off,         Ah + go, asz);
            cp16(sbs + CV_BH + off, Bh + gb, 16u);
        }
    };

    auto compute = [&](int buf) {
        uint32_t sb = sbase + buf * CV_STAGE;
#pragma unroll
        for (int h = 0; h < 2; h++) {
            uint32_t hb = (uint32_t)h * 32;
            uint32_t fah[4][4], fbh[4][2];
#pragma unroll
            for (int mt = 0; mt < 4; mt++)
                ldsm4(fah[mt][0], fah[mt][1], fah[mt][2], fah[mt][3],
                      sb + aoff[mt] + hb);
            ldsm4(fbh[0][0], fbh[1][0], fbh[2][0], fbh[3][0], sb + CV_BH + boff + hb);
            ldsm4(fbh[0][1], fbh[1][1], fbh[2][1], fbh[3][1], sb + CV_BH + boff + hb + 16);
#pragma unroll
            for (int mt = 0; mt < 4; mt++)
#pragma unroll
                for (int nt = 0; nt < 4; nt++)
                    mma_f16(acc[mt][nt], fah[mt], fbh[nt]);   // hi * hi only
        }
    };

    // 3-stage pipeline, depth-2 prefetch; one commit per iter keeps the
    // wait_group accounting exact (wait_group 1 => stage c has landed).
    issue_stage(0, 0); CP_COMMIT();
    issue_stage(1, 1); CP_COMMIT();
    for (int c = 0; c < nch; c++) {
        CP_WAIT1();
        __syncthreads();           // stage c visible; buf (c+2)%3 drained
        if (c + 2 < nch) issue_stage(c + 2, (c + 2) % 3);
        CP_COMMIT();
        compute(c % 3);
    }

    const int r0 = lane >> 2, cp = (lane & 3) * 2;
#pragma unroll
    for (int mt = 0; mt < 4; mt++) {
        int row = bm + wm + mt * 16 + r0;
#pragma unroll
        for (int nt = 0; nt < 4; nt++) {
            int col = bn + wn + nt * 8 + cp;
            float b0 = __ldg(bias + col);
            float b1 = __ldg(bias + col + 1);
            float o0 = fmaxf(acc[mt][nt][0] + b0, 0.f);
            float o1 = fmaxf(acc[mt][nt][1] + b1, 0.f);
            float o2 = fmaxf(acc[mt][nt][2] + b0, 0.f);
            float o3 = fmaxf(acc[mt][nt][3] + b1, 0.f);
            *(float2*)(C + (size_t)row * N + col)       = make_float2(o0, o1);
            *(float2*)(C + (size_t)(row + 8) * N + col) = make_float2(o2, o3);
        }
    }
}

// -------------------- dense GEMM: bf16x3, 2-stage cp.async (R11-proven) ----
#define MM_STAGE 40960
#define MM_SMEM  (2 * MM_STAGE)
#define OA_L 10240
#define OB_H 20480
#define OB_L 30720

__global__ void __launch_bounds__(256, 2)
mma_gemm(const __nv_bfloat16* __restrict__ Ah, const __nv_bfloat16* __restrict__ Al,
         const __nv_bfloat16* __restrict__ Bh, const __nv_bfloat16* __restrict__ Bl,
         float* __restrict__ C, int K, int N)
{
    extern __shared__ __align__(128) char smem[];
    const uint32_t sbase = smem_u32(smem);
    const int tid  = threadIdx.x;
    const int lane = tid & 31;
    const int wid  = tid >> 5;
    const int bm = blockIdx.y * 128;
    const int bn = blockIdx.x * 128;
    const int wm = (wid & 1) * 64;
    const int wn = (wid >> 1) * 32;
    const int nch = K >> 5;

    uint32_t aoff[4];
#pragma unroll
    for (int mt = 0; mt < 4; mt++)
        aoff[mt] = (uint32_t)(wm + mt * 16 + (lane & 15)) * 80 + ((lane >> 4) * 16);
    const uint32_t boff = (uint32_t)(wn + lane) * 80;

    float acc[4][4][4];
#pragma unroll
    for (int i = 0; i < 4; i++)
#pragma unroll
        for (int j = 0; j < 4; j++)
#pragma unroll
            for (int r = 0; r < 4; r++) acc[i][j][r] = 0.0f;

    const int l_r0 = tid >> 2;
    const int l_cq = tid & 3;
    const uint32_t l_soff = (uint32_t)l_r0 * 80 + l_cq * 16;

    auto issue_stage = [&](int c, int slot) {
        const int kt = c << 5;
        const uint32_t sbs = sbase + slot * MM_STAGE;
#pragma unroll
        for (int it = 0; it < 2; it++) {
            int row = l_r0 + it * 64;
            int cb = l_cq * 8;
            uint32_t off = l_soff + (uint32_t)it * (64 * 80);
            size_t go = (size_t)(bm + row) * K + kt + cb;
            size_t gb = (size_t)(bn + row) * K + kt + cb;
            cp16(sbs + off,        Ah + go, 16u);
            cp16(sbs + OA_L + off, Al + go, 16u);
            cp16(sbs + OB_H + off, Bh + gb, 16u);
            cp16(sbs + OB_L + off, Bl + gb, 16u);
        }
    };

    auto compute = [&](int buf) {
        uint32_t sb = sbase + buf * MM_STAGE;
#pragma unroll
        for (int h = 0; h < 2; h++) {
            uint32_t hb = (uint32_t)h * 32;
            uint32_t fah[4][4], fal[4][4], fbh[4][2], fbl[4][2];
#pragma unroll
            for (int mt = 0; mt < 4; mt++) {
                ldsm4(fah[mt][0], fah[mt][1], fah[mt][2], fah[mt][3],
                      sb + aoff[mt] + hb);
                ldsm4(fal[mt][0], fal[mt][1], fal[mt][2], fal[mt][3],
                      sb + OA_L + aoff[mt] + hb);
            }
            ldsm4(fbh[0][0], fbh[1][0], fbh[2][0], fbh[3][0], sb + OB_H + boff + hb);
            ldsm4(fbh[0][1], fbh[1][1], fbh[2][1], fbh[3][1], sb + OB_H + boff + hb + 16);
            ldsm4(fbl[0][0], fbl[1][0], fbl[2][0], fbl[3][0], sb + OB_L + boff + hb);
            ldsm4(fbl[0][1], fbl[1][1], fbl[2][1], fbl[3][1], sb + OB_L + boff + hb + 16);
#pragma unroll
            for (int mt = 0; mt < 4; mt++)
#pragma unroll
                for (int nt = 0; nt < 4; nt++) {
                    mma_bf16(acc[mt][nt], fah[mt], fbh[nt]);
                    mma_bf16(acc[mt][nt], fah[mt], fbl[nt]);
                    mma_bf16(acc[mt][nt], fal[mt], fbh[nt]);
                }
        }
    };

    issue_stage(0, 0);
    CP_COMMIT();
    for (int c = 0; c < nch; c++) {
        CP_WAIT0();
        __syncthreads();
        if (c + 1 < nch) { issue_stage(c + 1, (c + 1) & 1); CP_COMMIT(); }
        compute(c & 1);
    }

    const int r0 = lane >> 2, cp = (lane & 3) * 2;
#pragma unroll
    for (int mt = 0; mt < 4; mt++) {
        int row = bm + wm + mt * 16 + r0;
#pragma unroll
        for (int nt = 0; nt < 4; nt++) {
            int col = bn + wn + nt * 8 + cp;
            *(float2*)(C + (size_t)row * N + col) =
                make_float2(acc[mt][nt][0], acc[mt][nt][1]);
            *(float2*)(C + (size_t)(row + 8) * N + col) =
                make_float2(acc[mt][nt][2], acc[mt][nt][3]);
        }
    }
}

// -------------------- FFMA2 GEMM (small batched a@H, exact fp32) ------------
#define BM 128
#define BN 128
#define BK 16
#define APAD 4

__device__ __forceinline__ ull pack2(float lo, float hi) {
    ull r; asm("mov.b64 %0, {%1, %2};" : "=l"(r) : "f"(lo), "f"(hi)); return r;
}
__device__ __forceinline__ void fma2(ull& d, ull a, ull b) {
    asm("fma.rn.f32x2 %0, %1, %2, %0;" : "+l"(d) : "l"(a), "l"(b));
}
__device__ __forceinline__ float2 unpack2(ull v) {
    float2 f; asm("mov.b64 {%0, %1}, %2;" : "=f"(f.x), "=f"(f.y) : "l"(v)); return f;
}

__global__ void __launch_bounds__(256, 2)
ffma_gemm(const float* __restrict__ A, size_t sA,
          const float* __restrict__ B, size_t sB,
          float* __restrict__ C, size_t sC,
          const float* __restrict__ bias, int do_relu,
          int M, int N, int K)
{
    A += (size_t)blockIdx.z * sA;
    B += (size_t)blockIdx.z * sB;
    C += (size_t)blockIdx.z * sC;
    const int bm = blockIdx.y * BM;
    const int bn = blockIdx.x * BN;

    __shared__ float As[2][BK][BM + APAD];
    __shared__ float Bs[2][BK][BN];

    const int tid = threadIdx.x;
    const int tx = tid & 15;
    const int ty = tid >> 4;
    const int a_r = tid >> 2;
    const int a_c = (tid & 3) * 4;
    const int b_r = tid >> 5;
    const int b_c = (tid & 31) * 4;

    ull acc[8][4];
#pragma unroll
    for (int i = 0; i < 8; i++)
#pragma unroll
        for (int j = 0; j < 4; j++) acc[i][j] = 0ull;

    float4 ra0, ra1, rb0, rb1;

    auto load_tiles = [&](int kt) {
        ra0 = *(const float4*)(A + (size_t)(bm + a_r) * K + kt + a_c);
        ra1 = *(const float4*)(A + (size_t)(bm + a_r + 64) * K + kt + a_c);
        rb0 = *(const float4*)(B + (size_t)(kt + b_r) * N + bn + b_c);
        rb1 = *(const float4*)(B + (size_t)(kt + b_r + 8) * N + bn + b_c);
    };
    auto store_tiles = [&](int buf) {
        As[buf][a_c + 0][a_r] = ra0.x; As[buf][a_c + 1][a_r] = ra0.y;
        As[buf][a_c + 2][a_r] = ra0.z; As[buf][a_c + 3][a_r] = ra0.w;
        As[buf][a_c + 0][a_r + 64] = ra1.x; As[buf][a_c + 1][a_r + 64] = ra1.y;
        As[buf][a_c + 2][a_r + 64] = ra1.z; As[buf][a_c + 3][a_r + 64] = ra1.w;
        *(float4*)&Bs[buf][b_r][b_c] = rb0;
        *(float4*)&Bs[buf][b_r + 8][b_c] = rb1;
    };
    auto compute = [&](int buf) {
#pragma unroll
        for (int k = 0; k < BK; k++) {
            float4 a0 = *(const float4*)&As[buf][k][ty * 8];
            float4 a1 = *(const float4*)&As[buf][k][ty * 8 + 4];
            float4 b0 = *(const float4*)&Bs[buf][k][tx * 8];
            float4 b1 = *(const float4*)&Bs[buf][k][tx * 8 + 4];
            ull bp0 = pack2(b0.x, b0.y), bp1 = pack2(b0.z, b0.w);
            ull bp2 = pack2(b1.x, b1.y), bp3 = pack2(b1.z, b1.w);
            float av[8] = {a0.x, a0.y, a0.z, a0.w, a1.x, a1.y, a1.z, a1.w};
#pragma unroll
            for (int i = 0; i < 8; i++) {
                ull ap = pack2(av[i], av[i]);
                fma2(acc[i][0], ap, bp0); fma2(acc[i][1], ap, bp1);
                fma2(acc[i][2], ap, bp2); fma2(acc[i][3], ap, bp3);
            }
        }
    };

    load_tiles(0);
    store_tiles(0);
    __syncthreads();
    int buf = 0;
    for (int kt = BK;; kt += BK) {
        bool more = kt < K;
        if (more) load_tiles(kt);
        compute(buf);
        if (!more) break;
        store_tiles(buf ^ 1);
        __syncthreads();
        buf ^= 1;
    }

    float bv[8];
#pragma unroll
    for (int j = 0; j < 8; j++) bv[j] = bias ? bias[bn + tx * 8 + j] : 0.0f;

#pragma unroll
    for (int i = 0; i < 8; i++) {
        float o[8];
        float2 p;
        p = unpack2(acc[i][0]); o[0] = p.x + bv[0]; o[1] = p.y + bv[1];
        p = unpack2(acc[i][1]); o[2] = p.x + bv[2]; o[3] = p.y + bv[3];
        p = unpack2(acc[i][2]); o[4] = p.x + bv[4]; o[5] = p.y + bv[5];
        p = unpack2(acc[i][3]); o[6] = p.x + bv[6]; o[7] = p.y + bv[7];
        if (do_relu) {
#pragma unroll
            for (int j = 0; j < 8; j++) o[j] = fmaxf(o[j], 0.0f);
        }
        size_t off = (size_t)(bm + ty * 8 + i) * N + bn + tx * 8;
        *(float4*)(C + off)     = make_float4(o[0], o[1], o[2], o[3]);
        *(float4*)(C + off + 4) = make_float4(o[4], o[5], o[6], o[7]);
    }
}

// ---------------------------------------------------------------------------
extern "C" void kernel_launch(void* const* d_in, const int* in_sizes, int n_in,
                              void* d_out, int out_size) {
    const float* x      = (const float*)d_in[0];
    const float* nodes  = (const float*)d_in[1];
    const float* adj    = (const float*)d_in[2];
    const float* conv_w = (const float*)d_in[3];
    const float* conv_b = (const float*)d_in[4];
    const float* W1     = (const float*)d_in[5];
    const float* b1     = (const float*)d_in[6];
    const float* W2     = (const float*)d_in[7];
    const float* b2     = (const float*)d_in[8];

    float* feats   = (float*)d_out;
    float* gcn_out = (float*)d_out + (size_t)12 * 512 * 2048;

    __half *xh, *wh;
    __nv_bfloat16 *w1h, *w1l, *w2h, *w2l, *nh, *nl, *hh, *hl;
    float *anorm, *h1, *h2;
    cudaGetSymbolAddress((void**)&xh, g_xh16);
    cudaGetSymbolAddress((void**)&wh, g_wh16);
    cudaGetSymbolAddress((void**)&w1h, g_w1h);  cudaGetSymbolAddress((void**)&w1l, g_w1l);
    cudaGetSymbolAddress((void**)&w2h, g_w2h);  cudaGetSymbolAddress((void**)&w2l, g_w2l);
    cudaGetSymbolAddress((void**)&nh, g_nh);    cudaGetSymbolAddress((void**)&nl, g_nl);
    cudaGetSymbolAddress((void**)&hh, g_hh);    cudaGetSymbolAddress((void**)&hl, g_hl);
    cudaGetSymbolAddress((void**)&anorm, g_anorm);
    cudaGetSymbolAddress((void**)&h1, g_h1);    cudaGetSymbolAddress((void**)&h2, g_h2);

    cudaFuncSetAttribute((const void*)conv_gemm,
                         cudaFuncAttributeMaxDynamicSharedMemorySize, CV_SMEM);
    cudaFuncSetAttribute((const void*)mma_gemm,
                         cudaFuncAttributeMaxDynamicSharedMemorySize, MM_SMEM);

    const bool fork = (g_s2 != nullptr) && (g_ev_fork != nullptr) && (g_ev_join != nullptr);
    cudaStream_t sB = fork ? g_s2 : (cudaStream_t)0;

    if (fork) {
        cudaEventRecord(g_ev_fork, 0);
        cudaStreamWaitEvent(g_s2, g_ev_fork, 0);
    }

    // --- branch A (conv path, capture stream); conv = 4th kernel issued ---
    convw_f16_kernel<<<2048, 256>>>(conv_w);                         // (0)
    cast_f16_kernel<<<4096, 256>>>(x, xh, 12 * 512 * 2048);          // (1)
    norm_adj_kernel<<<1024, 256, 0, sB>>>(adj);                      // (2, branch B)
    conv_gemm<<<dim3(16, 48), 256, CV_SMEM>>>(                       // (3) <- profiled
        xh, wh, feats, conv_b, 6144, 2048);

    // --- branch B (GCN chain), independent of conv, bf16x3 + exact ffma ---
    transw_split_kernel<<<dim3(64, 64), dim3(32, 8), 0, sB>>>(W1, w1h, w1l);
    transw_split_kernel<<<dim3(64, 64), dim3(32, 8), 0, sB>>>(W2, w2h, w2l);
    split_kernel<<<2048, 256, 0, sB>>>(nodes, nh, nl, 1024 * 2048);
    mma_gemm<<<dim3(16, 8), 256, MM_SMEM, sB>>>(
        nh, nl, w1h, w1l, h1, 2048, 2048);
    ffma_gemm<<<dim3(16, 2, 4), 256, 0, sB>>>(
        anorm, 65536, h1, 524288, h2, 524288, b1, 1, 256, 2048, 256);
    split_kernel<<<2048, 256, 0, sB>>>(h2, hh, hl, 1024 * 2048);
    mma_gemm<<<dim3(16, 8), 256, MM_SMEM, sB>>>(
        hh, hl, w2h, w2l, h1, 2048, 2048);
    ffma_gemm<<<dim3(16, 2, 4), 256, 0, sB>>>(
        anorm, 65536, h1, 524288, gcn_out, 524288, b2, 0, 256, 2048, 256);

    if (fork) {
        cudaEventRecord(g_ev_join, g_s2);
        cudaStreamWaitEvent((cudaStream_t)0, g_ev_join, 0);
    }

    (void)in_sizes; (void)n_in; (void)out_size;
}